// round 12
// baseline (speedup 1.0000x reference)
#include <cuda_runtime.h>
#include <cuda_fp16.h>
#include <cstdint>

// Jacobian (3x12) of 3->64->64->64->64->12 SiLU MLP at N=1M points.
// mma.sync m16n8k16 fp16, fp32 accum. 2-term split ON WEIGHTS ONLY:
//   W = Wh + Wl (fp16 planes); product = x_f16*Wh + x_f16*Wl (residual ~2^-11).
// One warp owns a 16-point tile + ALL 4 vectors {h,t0,t1,t2}; D-accumulator
// fragments map register-locally onto next layer's A fragments.
// Vector-PAIRED GEMMs: each B fragment loaded once feeds two vectors' MMAs.
// 512 thr/CTA (4 warps/SMSP); t0,t1,t2 A-frags + dv in per-lane SMEM slots.
// R12: sigmoid via single tanh.approx MUFU (was ex2+rcp); accumulators
// bias-initialized (MMA accumulates onto bias; epilogue bias-add deleted).
//
// SMEM words: [0,192) W1 | [192,448) b1..b4 | [448,12736) B' L2..4
// (per layer: Wh 2048 | Wl 2048, SoA slot (kt*4+j)*32+lane) |
// [12736,13760) B5' (Wh 512 | Wl 512) |
// [13760,38336) A-frag slots: 16 warps x 3 vec x 4 kt x 32 lanes x uint4 |
// [38336,54720) dv slots: 16 warps x 8 x 32 lanes x float4
#define PD_THREADS 512
#define PD_NW 16
#define SM_W1   0
#define SM_BIAS 192
#define SM_B    448
#define SM_B5   12736
#define SM_A4   3440            /* uint4 index of A-frag area (word 13760/4) */
#define SM_DV4  9584            /* float4 index of dv area (word 38336/4) */
#define SM_WORDS 54720

__device__ __forceinline__ void pd_mma(float* d,
                                       uint32_t a0, uint32_t a1, uint32_t a2, uint32_t a3,
                                       uint32_t b0, uint32_t b1) {
    asm volatile(
        "mma.sync.aligned.m16n8k16.row.col.f32.f16.f16.f32 "
        "{%0,%1,%2,%3},{%4,%5,%6,%7},{%8,%9},{%0,%1,%2,%3};\n"
        : "+f"(d[0]), "+f"(d[1]), "+f"(d[2]), "+f"(d[3])
        : "r"(a0), "r"(a1), "r"(a2), "r"(a3), "r"(b0), "r"(b1));
}

__device__ __forceinline__ void pd_mma8(float* acc,
                                        uint32_t a0, uint32_t a1, uint32_t a2, uint32_t a3,
                                        uint4 B0, uint4 B1, uint4 B2, uint4 B3) {
    pd_mma(acc + 0,  a0, a1, a2, a3, B0.x, B0.y);
    pd_mma(acc + 4,  a0, a1, a2, a3, B0.z, B0.w);
    pd_mma(acc + 8,  a0, a1, a2, a3, B1.x, B1.y);
    pd_mma(acc + 12, a0, a1, a2, a3, B1.z, B1.w);
    pd_mma(acc + 16, a0, a1, a2, a3, B2.x, B2.y);
    pd_mma(acc + 20, a0, a1, a2, a3, B2.z, B2.w);
    pd_mma(acc + 24, a0, a1, a2, a3, B3.x, B3.y);
    pd_mma(acc + 28, a0, a1, a2, a3, B3.z, B3.w);
}

// Paired 64x64 GEMM: v0 A in registers, v1 A in per-lane SMEM; shared B loads.
__device__ __forceinline__ void pd_gemm64_pair_rs(float* acc0, float* acc1,
                                                  const uint4* Bb4,
                                                  const uint32_t* A0, const uint4* av1) {
    #pragma unroll
    for (int kt = 0; kt < 4; ++kt) {
        uint32_t p0 = A0[4*kt+0], p1 = A0[4*kt+1], p2 = A0[4*kt+2], p3 = A0[4*kt+3];
        uint4 Q = av1[kt * 32];
        uint4 B0 = Bb4[kt * 128],      B1 = Bb4[kt * 128 + 32];
        uint4 B2 = Bb4[kt * 128 + 64], B3 = Bb4[kt * 128 + 96];
        pd_mma8(acc0, p0, p1, p2, p3, B0, B1, B2, B3);   // v0 * Wh
        pd_mma8(acc1, Q.x, Q.y, Q.z, Q.w, B0, B1, B2, B3);
        B0 = Bb4[512 + kt * 128];      B1 = Bb4[512 + kt * 128 + 32];
        B2 = Bb4[512 + kt * 128 + 64]; B3 = Bb4[512 + kt * 128 + 96];
        pd_mma8(acc0, p0, p1, p2, p3, B0, B1, B2, B3);   // v0 * Wl
        pd_mma8(acc1, Q.x, Q.y, Q.z, Q.w, B0, B1, B2, B3);
    }
}

// Paired GEMM with both A operands in per-lane SMEM.
__device__ __forceinline__ void pd_gemm64_pair_ss(float* acc0, float* acc1,
                                                  const uint4* Bb4,
                                                  const uint4* av0, const uint4* av1) {
    #pragma unroll
    for (int kt = 0; kt < 4; ++kt) {
        uint4 P = av0[kt * 32];
        uint4 Q = av1[kt * 32];
        uint4 B0 = Bb4[kt * 128],      B1 = Bb4[kt * 128 + 32];
        uint4 B2 = Bb4[kt * 128 + 64], B3 = Bb4[kt * 128 + 96];
        pd_mma8(acc0, P.x, P.y, P.z, P.w, B0, B1, B2, B3);
        pd_mma8(acc1, Q.x, Q.y, Q.z, Q.w, B0, B1, B2, B3);
        B0 = Bb4[512 + kt * 128];      B1 = Bb4[512 + kt * 128 + 32];
        B2 = Bb4[512 + kt * 128 + 64]; B3 = Bb4[512 + kt * 128 + 96];
        pd_mma8(acc0, P.x, P.y, P.z, P.w, B0, B1, B2, B3);
        pd_mma8(acc1, Q.x, Q.y, Q.z, Q.w, B0, B1, B2, B3);
    }
}

// Layer-5 tri-GEMM (n=16): B loaded once per kt, feeds all 3 tangents (SMEM A).
__device__ __forceinline__ void pd_gemm16_tri(float* a0, float* a1, float* a2,
                                              const uint4* B5b4, const uint4* av1,
                                              const uint4* av2, const uint4* av3) {
    #pragma unroll
    for (int kt = 0; kt < 4; ++kt) {
        uint4 R = av1[kt * 32];
        uint4 P = av2[kt * 32];
        uint4 Q = av3[kt * 32];
        uint4 H  = B5b4[kt * 32];
        uint4 Lo = B5b4[128 + kt * 32];
        pd_mma(a0 + 0, R.x, R.y, R.z, R.w, H.x, H.y);
        pd_mma(a0 + 4, R.x, R.y, R.z, R.w, H.z, H.w);
        pd_mma(a1 + 0, P.x, P.y, P.z, P.w, H.x, H.y);
        pd_mma(a1 + 4, P.x, P.y, P.z, P.w, H.z, H.w);
        pd_mma(a2 + 0, Q.x, Q.y, Q.z, Q.w, H.x, H.y);
        pd_mma(a2 + 4, Q.x, Q.y, Q.z, Q.w, H.z, H.w);
        pd_mma(a0 + 0, R.x, R.y, R.z, R.w, Lo.x, Lo.y);
        pd_mma(a0 + 4, R.x, R.y, R.z, R.w, Lo.z, Lo.w);
        pd_mma(a1 + 0, P.x, P.y, P.z, P.w, Lo.x, Lo.y);
        pd_mma(a1 + 4, P.x, P.y, P.z, P.w, Lo.z, Lo.w);
        pd_mma(a2 + 0, Q.x, Q.y, Q.z, Q.w, Lo.x, Lo.y);
        pd_mma(a2 + 4, Q.x, Q.y, Q.z, Q.w, Lo.z, Lo.w);
    }
}

// silu + silu' via single-MUFU sigmoid: sig = 0.5*tanh(x/2) + 0.5
__device__ __forceinline__ void pd_silu_d(float pre, float& h, float& d) {
    float t;
    asm("tanh.approx.f32 %0, %1;" : "=f"(t) : "f"(0.5f * pre));
    float sig = fmaf(0.5f, t, 0.5f);
    h = pre * sig;
    d = fmaf(h, 1.0f - sig, sig);
}

// pack (f0 -> low half, f1 -> high half) as fp16x2
__device__ __forceinline__ uint32_t pd_h2(float f0, float f1) {
    uint32_t r;
    asm("cvt.rn.f16x2.f32 %0, %1, %2;" : "=r"(r) : "f"(f1), "f"(f0));
    return r;
}

// fp16 hi/lo split for weight staging (once per CTA)
__device__ __forceinline__ void pd_splitw(float f0, float f1, uint32_t& hi, uint32_t& lo) {
    __half2 hh = __floats2half2_rn(f0, f1);
    float2 bk = __half22float2(hh);
    __half2 ll = __floats2half2_rn(f0 - bk.x, f1 - bk.y);
    hi = *(uint32_t*)&hh;
    lo = *(uint32_t*)&ll;
}

__device__ __forceinline__ void pd_store(float* __restrict__ out, const float* a5,
                                         int pA, int pB, int N, int j, int tg) {
    if (pA < N) {
        float* o = out + 36 * (size_t)pA + 12 * j;
        *(float2*)(o + 2 * tg) = make_float2(a5[0], a5[1]);
        if (tg < 2) *(float2*)(o + 8 + 2 * tg) = make_float2(a5[4], a5[5]);
    }
    if (pB < N) {
        float* o = out + 36 * (size_t)pB + 12 * j;
        *(float2*)(o + 2 * tg) = make_float2(a5[2], a5[3]);
        if (tg < 2) *(float2*)(o + 8 + 2 * tg) = make_float2(a5[6], a5[7]);
    }
}

__global__ void __launch_bounds__(PD_THREADS, 1)
PartialDerivatives_38706245271665_kernel(
    const float* __restrict__ x,
    const float* __restrict__ W1, const float* __restrict__ b1,
    const float* __restrict__ W2, const float* __restrict__ b2,
    const float* __restrict__ W3, const float* __restrict__ b3,
    const float* __restrict__ W4, const float* __restrict__ b4,
    const float* __restrict__ W5,
    float* __restrict__ out, int N)
{
    extern __shared__ uint32_t sm[];
    float* sW1   = (float*)(sm + SM_W1);
    float* sBias = (float*)(sm + SM_BIAS);
    const int tid = threadIdx.x;

    // ---- stage W1 / biases ----
    for (int i = tid; i < 192; i += PD_THREADS) sW1[i] = W1[i];
    for (int i = tid; i < 64; i += PD_THREADS) {
        sBias[i] = b1[i]; sBias[64 + i] = b2[i];
        sBias[128 + i] = b3[i]; sBias[192 + i] = b4[i];
    }
    // ---- stage B' SoA: word r = ((kt*4+j)*32 + lane)*4 + c ----
    for (int i = tid; i < 3 * 2048; i += PD_THREADS) {
        int L = i >> 11, r = i & 2047;
        int c = r & 3, t = r >> 2;
        int lane_ = t & 31, jj = (t >> 5) & 3, kt = t >> 7;
        int tg_ = lane_ & 3, g_ = lane_ >> 2;
        int nt = 2 * jj + (c >> 1), rr = c & 1;
        int k0 = 16 * kt + 2 * tg_ + 8 * rr;
        int n  = 8 * nt + g_;
        const float* W = (L == 0) ? W2 : (L == 1) ? W3 : W4;
        uint32_t hi, lo;
        pd_splitw(W[k0 * 64 + n], W[(k0 + 1) * 64 + n], hi, lo);
        sm[SM_B + L * 4096 + r] = hi;
        sm[SM_B + L * 4096 + 2048 + r] = lo;
    }
    // ---- stage B5' SoA: word i = (kt*32 + lane)*4 + c ----
    for (int i = tid; i < 512; i += PD_THREADS) {
        int c = i & 3, t = i >> 2;
        int lane_ = t & 31, kt = t >> 5;
        int tg_ = lane_ & 3, g_ = lane_ >> 2;
        int nt = c >> 1, rr = c & 1;
        int k0 = 16 * kt + 2 * tg_ + 8 * rr;
        int n  = 8 * nt + g_;
        float v0 = (n < 12) ? W5[k0 * 12 + n] : 0.0f;
        float v1 = (n < 12) ? W5[(k0 + 1) * 12 + n] : 0.0f;
        uint32_t hi, lo;
        pd_splitw(v0, v1, hi, lo);
        sm[SM_B5 + i] = hi;
        sm[SM_B5 + 512 + i] = lo;
    }
    __syncthreads();

    const int wid  = tid >> 5;
    const int lane = tid & 31;
    const int g    = lane >> 2;
    const int tg   = lane & 3;

    const uint4* Bfrag4  = ((const uint4*)(sm + SM_B))  + lane;   // + L*1024 (uint4)
    const uint4* B5frag4 = ((const uint4*)(sm + SM_B5)) + lane;
    // Per-lane A-frag slots for t0/t1/t2 (same-thread rw only, conflict-free).
    uint4* av1 = ((uint4*)sm) + SM_A4 + wid * 384 + lane;
    uint4* av2 = av1 + 128;
    uint4* av3 = av1 + 256;
    // Per-lane dv slots: sdv[nt*32] holds dv[4nt..4nt+3].
    float4* sdv = ((float4*)sm) + SM_DV4 + wid * 256 + lane;

    const int nTiles = (N + 15) >> 4;

    for (int wt = blockIdx.x * PD_NW + wid; wt < nTiles; wt += gridDim.x * PD_NW) {
        const int p0 = wt << 4;
        const int pA = p0 + g, pB = p0 + g + 8;

        uint32_t Ah0[16];   // h fragments in registers

        // ================ layer 1 (K=3), direct into fragments ================
        {
            float xA0 = 0.f, xA1 = 0.f, xA2 = 0.f, xB0 = 0.f, xB1 = 0.f, xB2 = 0.f;
            if (pA < N) {
                const float* xp = x + 3 * (size_t)pA;
                xA0 = __ldg(xp); xA1 = __ldg(xp + 1); xA2 = __ldg(xp + 2);
            }
            if (pB < N) {
                const float* xp = x + 3 * (size_t)pB;
                xB0 = __ldg(xp); xB1 = __ldg(xp + 1); xB2 = __ldg(xp + 2);
            }
            #pragma unroll
            for (int kt = 0; kt < 4; ++kt) {
                uint32_t f1[4], f2[4], f3[4];
                #pragma unroll
                for (int s = 0; s < 2; ++s) {
                    int f0 = 16 * kt + 2 * tg + 8 * s;
                    float2 w0 = *(float2*)&sW1[f0];
                    float2 w1 = *(float2*)&sW1[64 + f0];
                    float2 w2 = *(float2*)&sW1[128 + f0];
                    float2 bb = *(float2*)&sBias[f0];
                    float hA0, dA0, hA1, dA1, hB0, dB0, hB1, dB1;
                    pd_silu_d(fmaf(xA0, w0.x, fmaf(xA1, w1.x, fmaf(xA2, w2.x, bb.x))), hA0, dA0);
                    pd_silu_d(fmaf(xA0, w0.y, fmaf(xA1, w1.y, fmaf(xA2, w2.y, bb.y))), hA1, dA1);
                    pd_silu_d(fmaf(xB0, w0.x, fmaf(xB1, w1.x, fmaf(xB2, w2.x, bb.x))), hB0, dB0);
                    pd_silu_d(fmaf(xB0, w0.y, fmaf(xB1, w1.y, fmaf(xB2, w2.y, bb.y))), hB1, dB1);
                    int fr = kt * 4 + 2 * s;
                    Ah0[fr]     = pd_h2(hA0, hA1);
                    Ah0[fr + 1] = pd_h2(hB0, hB1);
                    f1[2*s]   = pd_h2(w0.x * dA0, w0.y * dA1);
                    f1[2*s+1] = pd_h2(w0.x * dB0, w0.y * dB1);
                    f2[2*s]   = pd_h2(w1.x * dA0, w1.y * dA1);
                    f2[2*s+1] = pd_h2(w1.x * dB0, w1.y * dB1);
                    f3[2*s]   = pd_h2(w2.x * dA0, w2.y * dA1);
                    f3[2*s+1] = pd_h2(w2.x * dB0, w2.y * dB1);
                }
                av1[kt * 32] = make_uint4(f1[0], f1[1], f1[2], f1[3]);
                av2[kt * 32] = make_uint4(f2[0], f2[1], f2[2], f2[3]);
                av3[kt * 32] = make_uint4(f3[0], f3[1], f3[2], f3[3]);
            }
        }

        // ================ layers 2..4: paired MMA + per-kt fused epilogues ================
        #pragma unroll 1
        for (int L = 0; L < 3; ++L) {
            const uint4* Bb4  = Bfrag4 + L * 1024;
            const float* bias = sBias + 64 + L * 64;
            const bool lastL  = (L == 2);

            // ---- pair 1: (h regs, t0 smem), shared B loads ----
            {
                float acc0[32], acc1[32];
                // bias-init acc0 (MMA accumulates onto bias); zero-init acc1
                #pragma unroll
                for (int nt = 0; nt < 8; ++nt) {
                    float2 bb = *(float2*)&bias[8 * nt + 2 * tg];
                    acc0[4*nt+0] = bb.x; acc0[4*nt+1] = bb.y;
                    acc0[4*nt+2] = bb.x; acc0[4*nt+3] = bb.y;
                    acc1[4*nt+0] = 0.f;  acc1[4*nt+1] = 0.f;
                    acc1[4*nt+2] = 0.f;  acc1[4*nt+3] = 0.f;
                }
                pd_gemm64_pair_rs(acc0, acc1, Bb4, Ah0, av1);
                // epilogue fused per kt: silu on acc0 -> h,dv; dv to SMEM;
                // scale acc1 by dv; pack both.
                #pragma unroll
                for (int kt = 0; kt < 4; ++kt) {
                    float hv[8];
                    #pragma unroll
                    for (int s = 0; s < 2; ++s) {
                        int nt = 2 * kt + s;
                        float d0, d1, d2, d3;
                        pd_silu_d(acc0[4 * nt + 0], hv[4*s+0], d0);
                        pd_silu_d(acc0[4 * nt + 1], hv[4*s+1], d1);
                        pd_silu_d(acc0[4 * nt + 2], hv[4*s+2], d2);
                        pd_silu_d(acc0[4 * nt + 3], hv[4*s+3], d3);
                        sdv[nt * 32] = make_float4(d0, d1, d2, d3);
                        acc1[4 * nt + 0] *= d0; acc1[4 * nt + 1] *= d1;
                        acc1[4 * nt + 2] *= d2; acc1[4 * nt + 3] *= d3;
                    }
                    if (!lastL) {
                        Ah0[4*kt+0] = pd_h2(hv[0], hv[1]);
                        Ah0[4*kt+1] = pd_h2(hv[2], hv[3]);
                        Ah0[4*kt+2] = pd_h2(hv[4], hv[5]);
                        Ah0[4*kt+3] = pd_h2(hv[6], hv[7]);
                    }
                    av1[kt * 32] = make_uint4(pd_h2(acc1[8*kt+0], acc1[8*kt+1]),
                                              pd_h2(acc1[8*kt+2], acc1[8*kt+3]),
                                              pd_h2(acc1[8*kt+4], acc1[8*kt+5]),
                                              pd_h2(acc1[8*kt+6], acc1[8*kt+7]));
                }
            }
            // ---- pair 2: (t1, t2) smem A, shared B loads ----
            {
                float acc0[32], acc1[32];
                #pragma unroll
                for (int q = 0; q < 32; ++q) { acc0[q] = 0.f; acc1[q] = 0.f; }
                pd_gemm64_pair_ss(acc0, acc1, Bb4, av2, av3);
                #pragma unroll
                for (int kt = 0; kt < 4; ++kt) {
                    float4 dA = sdv[(2 * kt) * 32];
                    float4 dB = sdv[(2 * kt + 1) * 32];
                    acc0[8*kt+0] *= dA.x; acc0[8*kt+1] *= dA.y;
                    acc0[8*kt+2] *= dA.z; acc0[8*kt+3] *= dA.w;
                    acc0[8*kt+4] *= dB.x; acc0[8*kt+5] *= dB.y;
                    acc0[8*kt+6] *= dB.z; acc0[8*kt+7] *= dB.w;
                    acc1[8*kt+0] *= dA.x; acc1[8*kt+1] *= dA.y;
                    acc1[8*kt+2] *= dA.z; acc1[8*kt+3] *= dA.w;
                    acc1[8*kt+4] *= dB.x; acc1[8*kt+5] *= dB.y;
                    acc1[8*kt+6] *= dB.z; acc1[8*kt+7] *= dB.w;
                    av2[kt * 32] = make_uint4(pd_h2(acc0[8*kt+0], acc0[8*kt+1]),
                                              pd_h2(acc0[8*kt+2], acc0[8*kt+3]),
                                              pd_h2(acc0[8*kt+4], acc0[8*kt+5]),
                                              pd_h2(acc0[8*kt+6], acc0[8*kt+7]));
                    av3[kt * 32] = make_uint4(pd_h2(acc1[8*kt+0], acc1[8*kt+1]),
                                              pd_h2(acc1[8*kt+2], acc1[8*kt+3]),
                                              pd_h2(acc1[8*kt+4], acc1[8*kt+5]),
                                              pd_h2(acc1[8*kt+6], acc1[8*kt+7]));
                }
            }
        }

        // ================ layer 5: tri-GEMM, shared B loads ================
        {
            float a50[8], a51[8], a52[8];
            #pragma unroll
            for (int q = 0; q < 8; ++q) { a50[q] = 0.f; a51[q] = 0.f; a52[q] = 0.f; }
            pd_gemm16_tri(a50, a51, a52, B5frag4, av1, av2, av3);
            pd_store(out, a50, pA, pB, N, 0, tg);
            pd_store(out, a51, pA, pB, N, 1, tg);
            pd_store(out, a52, pA, pB, N, 2, tg);
        }
    }
}

extern "C" void kernel_launch(void* const* d_in, const int* in_sizes, int n_in,
                              void* d_out, int out_size)
{
    const float* x  = (const float*)d_in[0];
    const float* W1 = (const float*)d_in[1];
    const float* b1 = (const float*)d_in[2];
    const float* W2 = (const float*)d_in[3];
    const float* b2 = (const float*)d_in[4];
    const float* W3 = (const float*)d_in[5];
    const float* b3 = (const float*)d_in[6];
    const float* W4 = (const float*)d_in[7];
    const float* b4 = (const float*)d_in[8];
    const float* W5 = (const float*)d_in[9];
    // b5 unused: constant offset has zero Jacobian.

    int N = in_sizes[0] / 3;
    int smemBytes = SM_WORDS * (int)sizeof(uint32_t);   // 218880

    cudaFuncSetAttribute(PartialDerivatives_38706245271665_kernel,
                         cudaFuncAttributeMaxDynamicSharedMemorySize, smemBytes);

    // 152 persistent CTAs, 512 threads (16 warps) each -> 1 CTA/SM, 4 warps/SMSP.
    PartialDerivatives_38706245271665_kernel<<<152, PD_THREADS, smemBytes>>>(
        x, W1, b1, W2, b2, W3, b3, W4, b4, W5, (float*)d_out, N);
}

// round 13
// speedup vs baseline: 1.5300x; 1.5300x over previous
#include <cuda_runtime.h>
#include <cuda_fp16.h>
#include <cstdint>

// Jacobian (3x12) of 3->64->64->64->64->12 SiLU MLP at N=1M points.
// mma.sync m16n8k16 fp16, fp32 accum. 2-term split ON WEIGHTS ONLY:
//   W = Wh + Wl (fp16 planes); product = x_f16*Wh + x_f16*Wl (residual ~2^-11).
// One warp owns a 16-point tile + ALL 4 vectors {h,t0,t1,t2}; D-accumulator
// fragments map register-locally onto next layer's A fragments.
// Vector-PAIRED GEMMs: each B fragment loaded once feeds two vectors' MMAs.
// 512 thr/CTA (4 warps/SMSP); t0,t1,t2 A-frags + dv in per-lane SMEM slots.
// R13: R11 structure EXACTLY (zero-init accs, post-GEMM bias add — R12's
// bias-init pushed regs to the 128 cap and spilled), plus the validated
// single-MUFU sigmoid: sig = 0.5*tanh(x/2)+0.5 (rel_err delta +5e-8 in R12).
//
// SMEM words: [0,192) W1 | [192,448) b1..b4 | [448,12736) B' L2..4
// (per layer: Wh 2048 | Wl 2048, SoA slot (kt*4+j)*32+lane) |
// [12736,13760) B5' (Wh 512 | Wl 512) |
// [13760,38336) A-frag slots: 16 warps x 3 vec x 4 kt x 32 lanes x uint4 |
// [38336,54720) dv slots: 16 warps x 8 x 32 lanes x float4
#define PD_THREADS 512
#define PD_NW 16
#define SM_W1   0
#define SM_BIAS 192
#define SM_B    448
#define SM_B5   12736
#define SM_A4   3440            /* uint4 index of A-frag area (word 13760/4) */
#define SM_DV4  9584            /* float4 index of dv area (word 38336/4) */
#define SM_WORDS 54720

__device__ __forceinline__ void pd_mma(float* d,
                                       uint32_t a0, uint32_t a1, uint32_t a2, uint32_t a3,
                                       uint32_t b0, uint32_t b1) {
    asm volatile(
        "mma.sync.aligned.m16n8k16.row.col.f32.f16.f16.f32 "
        "{%0,%1,%2,%3},{%4,%5,%6,%7},{%8,%9},{%0,%1,%2,%3};\n"
        : "+f"(d[0]), "+f"(d[1]), "+f"(d[2]), "+f"(d[3])
        : "r"(a0), "r"(a1), "r"(a2), "r"(a3), "r"(b0), "r"(b1));
}

__device__ __forceinline__ void pd_mma8(float* acc,
                                        uint32_t a0, uint32_t a1, uint32_t a2, uint32_t a3,
                                        uint4 B0, uint4 B1, uint4 B2, uint4 B3) {
    pd_mma(acc + 0,  a0, a1, a2, a3, B0.x, B0.y);
    pd_mma(acc + 4,  a0, a1, a2, a3, B0.z, B0.w);
    pd_mma(acc + 8,  a0, a1, a2, a3, B1.x, B1.y);
    pd_mma(acc + 12, a0, a1, a2, a3, B1.z, B1.w);
    pd_mma(acc + 16, a0, a1, a2, a3, B2.x, B2.y);
    pd_mma(acc + 20, a0, a1, a2, a3, B2.z, B2.w);
    pd_mma(acc + 24, a0, a1, a2, a3, B3.x, B3.y);
    pd_mma(acc + 28, a0, a1, a2, a3, B3.z, B3.w);
}

// Paired 64x64 GEMM: v0 A in registers, v1 A in per-lane SMEM; shared B loads.
__device__ __forceinline__ void pd_gemm64_pair_rs(float* acc0, float* acc1,
                                                  const uint4* Bb4,
                                                  const uint32_t* A0, const uint4* av1) {
    #pragma unroll
    for (int kt = 0; kt < 4; ++kt) {
        uint32_t p0 = A0[4*kt+0], p1 = A0[4*kt+1], p2 = A0[4*kt+2], p3 = A0[4*kt+3];
        uint4 Q = av1[kt * 32];
        uint4 B0 = Bb4[kt * 128],      B1 = Bb4[kt * 128 + 32];
        uint4 B2 = Bb4[kt * 128 + 64], B3 = Bb4[kt * 128 + 96];
        pd_mma8(acc0, p0, p1, p2, p3, B0, B1, B2, B3);   // v0 * Wh
        pd_mma8(acc1, Q.x, Q.y, Q.z, Q.w, B0, B1, B2, B3);
        B0 = Bb4[512 + kt * 128];      B1 = Bb4[512 + kt * 128 + 32];
        B2 = Bb4[512 + kt * 128 + 64]; B3 = Bb4[512 + kt * 128 + 96];
        pd_mma8(acc0, p0, p1, p2, p3, B0, B1, B2, B3);   // v0 * Wl
        pd_mma8(acc1, Q.x, Q.y, Q.z, Q.w, B0, B1, B2, B3);
    }
}

// Paired GEMM with both A operands in per-lane SMEM.
__device__ __forceinline__ void pd_gemm64_pair_ss(float* acc0, float* acc1,
                                                  const uint4* Bb4,
                                                  const uint4* av0, const uint4* av1) {
    #pragma unroll
    for (int kt = 0; kt < 4; ++kt) {
        uint4 P = av0[kt * 32];
        uint4 Q = av1[kt * 32];
        uint4 B0 = Bb4[kt * 128],      B1 = Bb4[kt * 128 + 32];
        uint4 B2 = Bb4[kt * 128 + 64], B3 = Bb4[kt * 128 + 96];
        pd_mma8(acc0, P.x, P.y, P.z, P.w, B0, B1, B2, B3);
        pd_mma8(acc1, Q.x, Q.y, Q.z, Q.w, B0, B1, B2, B3);
        B0 = Bb4[512 + kt * 128];      B1 = Bb4[512 + kt * 128 + 32];
        B2 = Bb4[512 + kt * 128 + 64]; B3 = Bb4[512 + kt * 128 + 96];
        pd_mma8(acc0, P.x, P.y, P.z, P.w, B0, B1, B2, B3);
        pd_mma8(acc1, Q.x, Q.y, Q.z, Q.w, B0, B1, B2, B3);
    }
}

// Layer-5 tri-GEMM (n=16): B loaded once per kt, feeds all 3 tangents (SMEM A).
__device__ __forceinline__ void pd_gemm16_tri(float* a0, float* a1, float* a2,
                                              const uint4* B5b4, const uint4* av1,
                                              const uint4* av2, const uint4* av3) {
    #pragma unroll
    for (int kt = 0; kt < 4; ++kt) {
        uint4 R = av1[kt * 32];
        uint4 P = av2[kt * 32];
        uint4 Q = av3[kt * 32];
        uint4 H  = B5b4[kt * 32];
        uint4 Lo = B5b4[128 + kt * 32];
        pd_mma(a0 + 0, R.x, R.y, R.z, R.w, H.x, H.y);
        pd_mma(a0 + 4, R.x, R.y, R.z, R.w, H.z, H.w);
        pd_mma(a1 + 0, P.x, P.y, P.z, P.w, H.x, H.y);
        pd_mma(a1 + 4, P.x, P.y, P.z, P.w, H.z, H.w);
        pd_mma(a2 + 0, Q.x, Q.y, Q.z, Q.w, H.x, H.y);
        pd_mma(a2 + 4, Q.x, Q.y, Q.z, Q.w, H.z, H.w);
        pd_mma(a0 + 0, R.x, R.y, R.z, R.w, Lo.x, Lo.y);
        pd_mma(a0 + 4, R.x, R.y, R.z, R.w, Lo.z, Lo.w);
        pd_mma(a1 + 0, P.x, P.y, P.z, P.w, Lo.x, Lo.y);
        pd_mma(a1 + 4, P.x, P.y, P.z, P.w, Lo.z, Lo.w);
        pd_mma(a2 + 0, Q.x, Q.y, Q.z, Q.w, Lo.x, Lo.y);
        pd_mma(a2 + 4, Q.x, Q.y, Q.z, Q.w, Lo.z, Lo.w);
    }
}

// silu + silu' via single-MUFU sigmoid: sig = 0.5*tanh(x/2) + 0.5
// (validated in R12: rel_err delta vs __expf was +5e-8)
__device__ __forceinline__ void pd_silu_d(float pre, float& h, float& d) {
    float t;
    asm("tanh.approx.f32 %0, %1;" : "=f"(t) : "f"(0.5f * pre));
    float sig = fmaf(0.5f, t, 0.5f);
    h = pre * sig;
    d = fmaf(h, 1.0f - sig, sig);
}

// pack (f0 -> low half, f1 -> high half) as fp16x2
__device__ __forceinline__ uint32_t pd_h2(float f0, float f1) {
    uint32_t r;
    asm("cvt.rn.f16x2.f32 %0, %1, %2;" : "=r"(r) : "f"(f1), "f"(f0));
    return r;
}

// fp16 hi/lo split for weight staging (once per CTA)
__device__ __forceinline__ void pd_splitw(float f0, float f1, uint32_t& hi, uint32_t& lo) {
    __half2 hh = __floats2half2_rn(f0, f1);
    float2 bk = __half22float2(hh);
    __half2 ll = __floats2half2_rn(f0 - bk.x, f1 - bk.y);
    hi = *(uint32_t*)&hh;
    lo = *(uint32_t*)&ll;
}

__device__ __forceinline__ void pd_store(float* __restrict__ out, const float* a5,
                                         int pA, int pB, int N, int j, int tg) {
    if (pA < N) {
        float* o = out + 36 * (size_t)pA + 12 * j;
        *(float2*)(o + 2 * tg) = make_float2(a5[0], a5[1]);
        if (tg < 2) *(float2*)(o + 8 + 2 * tg) = make_float2(a5[4], a5[5]);
    }
    if (pB < N) {
        float* o = out + 36 * (size_t)pB + 12 * j;
        *(float2*)(o + 2 * tg) = make_float2(a5[2], a5[3]);
        if (tg < 2) *(float2*)(o + 8 + 2 * tg) = make_float2(a5[6], a5[7]);
    }
}

__global__ void __launch_bounds__(PD_THREADS, 1)
PartialDerivatives_38706245271665_kernel(
    const float* __restrict__ x,
    const float* __restrict__ W1, const float* __restrict__ b1,
    const float* __restrict__ W2, const float* __restrict__ b2,
    const float* __restrict__ W3, const float* __restrict__ b3,
    const float* __restrict__ W4, const float* __restrict__ b4,
    const float* __restrict__ W5,
    float* __restrict__ out, int N)
{
    extern __shared__ uint32_t sm[];
    float* sW1   = (float*)(sm + SM_W1);
    float* sBias = (float*)(sm + SM_BIAS);
    const int tid = threadIdx.x;

    // ---- stage W1 / biases ----
    for (int i = tid; i < 192; i += PD_THREADS) sW1[i] = W1[i];
    for (int i = tid; i < 64; i += PD_THREADS) {
        sBias[i] = b1[i]; sBias[64 + i] = b2[i];
        sBias[128 + i] = b3[i]; sBias[192 + i] = b4[i];
    }
    // ---- stage B' SoA: word r = ((kt*4+j)*32 + lane)*4 + c ----
    for (int i = tid; i < 3 * 2048; i += PD_THREADS) {
        int L = i >> 11, r = i & 2047;
        int c = r & 3, t = r >> 2;
        int lane_ = t & 31, jj = (t >> 5) & 3, kt = t >> 7;
        int tg_ = lane_ & 3, g_ = lane_ >> 2;
        int nt = 2 * jj + (c >> 1), rr = c & 1;
        int k0 = 16 * kt + 2 * tg_ + 8 * rr;
        int n  = 8 * nt + g_;
        const float* W = (L == 0) ? W2 : (L == 1) ? W3 : W4;
        uint32_t hi, lo;
        pd_splitw(W[k0 * 64 + n], W[(k0 + 1) * 64 + n], hi, lo);
        sm[SM_B + L * 4096 + r] = hi;
        sm[SM_B + L * 4096 + 2048 + r] = lo;
    }
    // ---- stage B5' SoA: word i = (kt*32 + lane)*4 + c ----
    for (int i = tid; i < 512; i += PD_THREADS) {
        int c = i & 3, t = i >> 2;
        int lane_ = t & 31, kt = t >> 5;
        int tg_ = lane_ & 3, g_ = lane_ >> 2;
        int nt = c >> 1, rr = c & 1;
        int k0 = 16 * kt + 2 * tg_ + 8 * rr;
        int n  = 8 * nt + g_;
        float v0 = (n < 12) ? W5[k0 * 12 + n] : 0.0f;
        float v1 = (n < 12) ? W5[(k0 + 1) * 12 + n] : 0.0f;
        uint32_t hi, lo;
        pd_splitw(v0, v1, hi, lo);
        sm[SM_B5 + i] = hi;
        sm[SM_B5 + 512 + i] = lo;
    }
    __syncthreads();

    const int wid  = tid >> 5;
    const int lane = tid & 31;
    const int g    = lane >> 2;
    const int tg   = lane & 3;

    const uint4* Bfrag4  = ((const uint4*)(sm + SM_B))  + lane;   // + L*1024 (uint4)
    const uint4* B5frag4 = ((const uint4*)(sm + SM_B5)) + lane;
    // Per-lane A-frag slots for t0/t1/t2 (same-thread rw only, conflict-free).
    uint4* av1 = ((uint4*)sm) + SM_A4 + wid * 384 + lane;
    uint4* av2 = av1 + 128;
    uint4* av3 = av1 + 256;
    // Per-lane dv slots: sdv[nt*32] holds dv[4nt..4nt+3].
    float4* sdv = ((float4*)sm) + SM_DV4 + wid * 256 + lane;

    const int nTiles = (N + 15) >> 4;

    for (int wt = blockIdx.x * PD_NW + wid; wt < nTiles; wt += gridDim.x * PD_NW) {
        const int p0 = wt << 4;
        const int pA = p0 + g, pB = p0 + g + 8;

        uint32_t Ah0[16];   // h fragments in registers

        // ================ layer 1 (K=3), direct into fragments ================
        {
            float xA0 = 0.f, xA1 = 0.f, xA2 = 0.f, xB0 = 0.f, xB1 = 0.f, xB2 = 0.f;
            if (pA < N) {
                const float* xp = x + 3 * (size_t)pA;
                xA0 = __ldg(xp); xA1 = __ldg(xp + 1); xA2 = __ldg(xp + 2);
            }
            if (pB < N) {
                const float* xp = x + 3 * (size_t)pB;
                xB0 = __ldg(xp); xB1 = __ldg(xp + 1); xB2 = __ldg(xp + 2);
            }
            #pragma unroll
            for (int kt = 0; kt < 4; ++kt) {
                uint32_t f1[4], f2[4], f3[4];
                #pragma unroll
                for (int s = 0; s < 2; ++s) {
                    int f0 = 16 * kt + 2 * tg + 8 * s;
                    float2 w0 = *(float2*)&sW1[f0];
                    float2 w1 = *(float2*)&sW1[64 + f0];
                    float2 w2 = *(float2*)&sW1[128 + f0];
                    float2 bb = *(float2*)&sBias[f0];
                    float hA0, dA0, hA1, dA1, hB0, dB0, hB1, dB1;
                    pd_silu_d(fmaf(xA0, w0.x, fmaf(xA1, w1.x, fmaf(xA2, w2.x, bb.x))), hA0, dA0);
                    pd_silu_d(fmaf(xA0, w0.y, fmaf(xA1, w1.y, fmaf(xA2, w2.y, bb.y))), hA1, dA1);
                    pd_silu_d(fmaf(xB0, w0.x, fmaf(xB1, w1.x, fmaf(xB2, w2.x, bb.x))), hB0, dB0);
                    pd_silu_d(fmaf(xB0, w0.y, fmaf(xB1, w1.y, fmaf(xB2, w2.y, bb.y))), hB1, dB1);
                    int fr = kt * 4 + 2 * s;
                    Ah0[fr]     = pd_h2(hA0, hA1);
                    Ah0[fr + 1] = pd_h2(hB0, hB1);
                    f1[2*s]   = pd_h2(w0.x * dA0, w0.y * dA1);
                    f1[2*s+1] = pd_h2(w0.x * dB0, w0.y * dB1);
                    f2[2*s]   = pd_h2(w1.x * dA0, w1.y * dA1);
                    f2[2*s+1] = pd_h2(w1.x * dB0, w1.y * dB1);
                    f3[2*s]   = pd_h2(w2.x * dA0, w2.y * dA1);
                    f3[2*s+1] = pd_h2(w2.x * dB0, w2.y * dB1);
                }
                av1[kt * 32] = make_uint4(f1[0], f1[1], f1[2], f1[3]);
                av2[kt * 32] = make_uint4(f2[0], f2[1], f2[2], f2[3]);
                av3[kt * 32] = make_uint4(f3[0], f3[1], f3[2], f3[3]);
            }
        }

        // ================ layers 2..4: paired MMA + per-kt fused epilogues ================
        #pragma unroll 1
        for (int L = 0; L < 3; ++L) {
            const uint4* Bb4  = Bfrag4 + L * 1024;
            const float* bias = sBias + 64 + L * 64;
            const bool lastL  = (L == 2);

            // ---- pair 1: (h regs, t0 smem), shared B loads ----
            {
                float acc0[32], acc1[32];
                #pragma unroll
                for (int q = 0; q < 32; ++q) { acc0[q] = 0.f; acc1[q] = 0.f; }
                pd_gemm64_pair_rs(acc0, acc1, Bb4, Ah0, av1);
                // epilogue fused per kt: silu on acc0 -> h,dv; dv to SMEM;
                // scale acc1 by dv; pack both.
                #pragma unroll
                for (int kt = 0; kt < 4; ++kt) {
                    float hv[8];
                    #pragma unroll
                    for (int s = 0; s < 2; ++s) {
                        int nt = 2 * kt + s;
                        float2 bb = *(float2*)&bias[8 * nt + 2 * tg];
                        float d0, d1, d2, d3;
                        pd_silu_d(acc0[4 * nt + 0] + bb.x, hv[4*s+0], d0);
                        pd_silu_d(acc0[4 * nt + 1] + bb.y, hv[4*s+1], d1);
                        pd_silu_d(acc0[4 * nt + 2] + bb.x, hv[4*s+2], d2);
                        pd_silu_d(acc0[4 * nt + 3] + bb.y, hv[4*s+3], d3);
                        sdv[nt * 32] = make_float4(d0, d1, d2, d3);
                        acc1[4 * nt + 0] *= d0; acc1[4 * nt + 1] *= d1;
                        acc1[4 * nt + 2] *= d2; acc1[4 * nt + 3] *= d3;
                    }
                    if (!lastL) {
                        Ah0[4*kt+0] = pd_h2(hv[0], hv[1]);
                        Ah0[4*kt+1] = pd_h2(hv[2], hv[3]);
                        Ah0[4*kt+2] = pd_h2(hv[4], hv[5]);
                        Ah0[4*kt+3] = pd_h2(hv[6], hv[7]);
                    }
                    av1[kt * 32] = make_uint4(pd_h2(acc1[8*kt+0], acc1[8*kt+1]),
                                              pd_h2(acc1[8*kt+2], acc1[8*kt+3]),
                                              pd_h2(acc1[8*kt+4], acc1[8*kt+5]),
                                              pd_h2(acc1[8*kt+6], acc1[8*kt+7]));
                }
            }
            // ---- pair 2: (t1, t2) smem A, shared B loads ----
            {
                float acc0[32], acc1[32];
                #pragma unroll
                for (int q = 0; q < 32; ++q) { acc0[q] = 0.f; acc1[q] = 0.f; }
                pd_gemm64_pair_ss(acc0, acc1, Bb4, av2, av3);
                #pragma unroll
                for (int kt = 0; kt < 4; ++kt) {
                    float4 dA = sdv[(2 * kt) * 32];
                    float4 dB = sdv[(2 * kt + 1) * 32];
                    acc0[8*kt+0] *= dA.x; acc0[8*kt+1] *= dA.y;
                    acc0[8*kt+2] *= dA.z; acc0[8*kt+3] *= dA.w;
                    acc0[8*kt+4] *= dB.x; acc0[8*kt+5] *= dB.y;
                    acc0[8*kt+6] *= dB.z; acc0[8*kt+7] *= dB.w;
                    acc1[8*kt+0] *= dA.x; acc1[8*kt+1] *= dA.y;
                    acc1[8*kt+2] *= dA.z; acc1[8*kt+3] *= dA.w;
                    acc1[8*kt+4] *= dB.x; acc1[8*kt+5] *= dB.y;
                    acc1[8*kt+6] *= dB.z; acc1[8*kt+7] *= dB.w;
                    av2[kt * 32] = make_uint4(pd_h2(acc0[8*kt+0], acc0[8*kt+1]),
                                              pd_h2(acc0[8*kt+2], acc0[8*kt+3]),
                                              pd_h2(acc0[8*kt+4], acc0[8*kt+5]),
                                              pd_h2(acc0[8*kt+6], acc0[8*kt+7]));
                    av3[kt * 32] = make_uint4(pd_h2(acc1[8*kt+0], acc1[8*kt+1]),
                                              pd_h2(acc1[8*kt+2], acc1[8*kt+3]),
                                              pd_h2(acc1[8*kt+4], acc1[8*kt+5]),
                                              pd_h2(acc1[8*kt+6], acc1[8*kt+7]));
                }
            }
        }

        // ================ layer 5: tri-GEMM, shared B loads ================
        {
            float a50[8], a51[8], a52[8];
            #pragma unroll
            for (int q = 0; q < 8; ++q) { a50[q] = 0.f; a51[q] = 0.f; a52[q] = 0.f; }
            pd_gemm16_tri(a50, a51, a52, B5frag4, av1, av2, av3);
            pd_store(out, a50, pA, pB, N, 0, tg);
            pd_store(out, a51, pA, pB, N, 1, tg);
            pd_store(out, a52, pA, pB, N, 2, tg);
        }
    }
}

extern "C" void kernel_launch(void* const* d_in, const int* in_sizes, int n_in,
                              void* d_out, int out_size)
{
    const float* x  = (const float*)d_in[0];
    const float* W1 = (const float*)d_in[1];
    const float* b1 = (const float*)d_in[2];
    const float* W2 = (const float*)d_in[3];
    const float* b2 = (const float*)d_in[4];
    const float* W3 = (const float*)d_in[5];
    const float* b3 = (const float*)d_in[6];
    const float* W4 = (const float*)d_in[7];
    const float* b4 = (const float*)d_in[8];
    const float* W5 = (const float*)d_in[9];
    // b5 unused: constant offset has zero Jacobian.

    int N = in_sizes[0] / 3;
    int smemBytes = SM_WORDS * (int)sizeof(uint32_t);   // 218880

    cudaFuncSetAttribute(PartialDerivatives_38706245271665_kernel,
                         cudaFuncAttributeMaxDynamicSharedMemorySize, smemBytes);

    // 152 persistent CTAs, 512 threads (16 warps) each -> 1 CTA/SM, 4 warps/SMSP.
    PartialDerivatives_38706245271665_kernel<<<152, PD_THREADS, smemBytes>>>(
        x, W1, b1, W2, b2, W3, b3, W4, b4, W5, (float*)d_out, N);
}

// round 14
// speedup vs baseline: 2.4432x; 1.5969x over previous
#include <cuda_runtime.h>
#include <cuda_fp16.h>
#include <cstdint>

// Jacobian (3x12) of 3->64->64->64->64->12 SiLU MLP at N=1M points.
// mma.sync m16n8k16 fp16, fp32 accum. R14: PURE fp16 weights (single plane,
// Wl residual plane dropped): weight-rounding ~2^-11 rel per layer lands
// inside the error budget (predicted ~6e-4 < 1e-3); MMA count and B LDS halve.
// One warp owns a 16-point tile + ALL 4 vectors {h,t0,t1,t2}; D-accumulator
// fragments map register-locally onto next layer's A fragments.
// Vector-PAIRED GEMMs: each B fragment loaded once feeds two vectors' MMAs.
// 512 thr/CTA (4 warps/SMSP); t0,t1,t2 A-frags + dv in per-lane SMEM slots.
// Sigmoid via single tanh.approx MUFU (validated R12/R13).
//
// SMEM words: [0,192) W1 | [192,448) b1..b4 | [448,6592) B' L2..4
// (2048 words/layer, SoA slot (kt*4+j)*32+lane) | [6592,7104) B5' |
// [7104,31680) A-frag slots: 16 warps x 3 vec x 4 kt x 32 lanes x uint4 |
// [31680,48064) dv slots: 16 warps x 8 x 32 lanes x float4
#define PD_THREADS 512
#define PD_NW 16
#define SM_W1   0
#define SM_BIAS 192
#define SM_B    448
#define SM_B5   6592
#define SM_A4   1776            /* uint4 index of A-frag area (word 7104/4) */
#define SM_DV4  7920            /* float4 index of dv area (word 31680/4) */
#define SM_WORDS 48064

__device__ __forceinline__ void pd_mma(float* d,
                                       uint32_t a0, uint32_t a1, uint32_t a2, uint32_t a3,
                                       uint32_t b0, uint32_t b1) {
    asm volatile(
        "mma.sync.aligned.m16n8k16.row.col.f32.f16.f16.f32 "
        "{%0,%1,%2,%3},{%4,%5,%6,%7},{%8,%9},{%0,%1,%2,%3};\n"
        : "+f"(d[0]), "+f"(d[1]), "+f"(d[2]), "+f"(d[3])
        : "r"(a0), "r"(a1), "r"(a2), "r"(a3), "r"(b0), "r"(b1));
}

__device__ __forceinline__ void pd_mma8(float* acc,
                                        uint32_t a0, uint32_t a1, uint32_t a2, uint32_t a3,
                                        uint4 B0, uint4 B1, uint4 B2, uint4 B3) {
    pd_mma(acc + 0,  a0, a1, a2, a3, B0.x, B0.y);
    pd_mma(acc + 4,  a0, a1, a2, a3, B0.z, B0.w);
    pd_mma(acc + 8,  a0, a1, a2, a3, B1.x, B1.y);
    pd_mma(acc + 12, a0, a1, a2, a3, B1.z, B1.w);
    pd_mma(acc + 16, a0, a1, a2, a3, B2.x, B2.y);
    pd_mma(acc + 20, a0, a1, a2, a3, B2.z, B2.w);
    pd_mma(acc + 24, a0, a1, a2, a3, B3.x, B3.y);
    pd_mma(acc + 28, a0, a1, a2, a3, B3.z, B3.w);
}

// Paired 64x64 GEMM (single weight plane): v0 A in regs, v1 A in per-lane SMEM.
__device__ __forceinline__ void pd_gemm64_pair_rs(float* acc0, float* acc1,
                                                  const uint4* Bb4,
                                                  const uint32_t* A0, const uint4* av1) {
    #pragma unroll
    for (int kt = 0; kt < 4; ++kt) {
        uint32_t p0 = A0[4*kt+0], p1 = A0[4*kt+1], p2 = A0[4*kt+2], p3 = A0[4*kt+3];
        uint4 Q = av1[kt * 32];
        uint4 B0 = Bb4[kt * 128],      B1 = Bb4[kt * 128 + 32];
        uint4 B2 = Bb4[kt * 128 + 64], B3 = Bb4[kt * 128 + 96];
        pd_mma8(acc0, p0, p1, p2, p3, B0, B1, B2, B3);
        pd_mma8(acc1, Q.x, Q.y, Q.z, Q.w, B0, B1, B2, B3);
    }
}

// Paired GEMM with both A operands in per-lane SMEM.
__device__ __forceinline__ void pd_gemm64_pair_ss(float* acc0, float* acc1,
                                                  const uint4* Bb4,
                                                  const uint4* av0, const uint4* av1) {
    #pragma unroll
    for (int kt = 0; kt < 4; ++kt) {
        uint4 P = av0[kt * 32];
        uint4 Q = av1[kt * 32];
        uint4 B0 = Bb4[kt * 128],      B1 = Bb4[kt * 128 + 32];
        uint4 B2 = Bb4[kt * 128 + 64], B3 = Bb4[kt * 128 + 96];
        pd_mma8(acc0, P.x, P.y, P.z, P.w, B0, B1, B2, B3);
        pd_mma8(acc1, Q.x, Q.y, Q.z, Q.w, B0, B1, B2, B3);
    }
}

// Layer-5 tri-GEMM (n=16, single plane): B loaded once per kt, 3 tangents.
__device__ __forceinline__ void pd_gemm16_tri(float* a0, float* a1, float* a2,
                                              const uint4* B5b4, const uint4* av1,
                                              const uint4* av2, const uint4* av3) {
    #pragma unroll
    for (int kt = 0; kt < 4; ++kt) {
        uint4 R = av1[kt * 32];
        uint4 P = av2[kt * 32];
        uint4 Q = av3[kt * 32];
        uint4 H = B5b4[kt * 32];
        pd_mma(a0 + 0, R.x, R.y, R.z, R.w, H.x, H.y);
        pd_mma(a0 + 4, R.x, R.y, R.z, R.w, H.z, H.w);
        pd_mma(a1 + 0, P.x, P.y, P.z, P.w, H.x, H.y);
        pd_mma(a1 + 4, P.x, P.y, P.z, P.w, H.z, H.w);
        pd_mma(a2 + 0, Q.x, Q.y, Q.z, Q.w, H.x, H.y);
        pd_mma(a2 + 4, Q.x, Q.y, Q.z, Q.w, H.z, H.w);
    }
}

// silu + silu' via single-MUFU sigmoid: sig = 0.5*tanh(x/2) + 0.5
__device__ __forceinline__ void pd_silu_d(float pre, float& h, float& d) {
    float t;
    asm("tanh.approx.f32 %0, %1;" : "=f"(t) : "f"(0.5f * pre));
    float sig = fmaf(0.5f, t, 0.5f);
    h = pre * sig;
    d = fmaf(h, 1.0f - sig, sig);
}

// pack (f0 -> low half, f1 -> high half) as fp16x2
__device__ __forceinline__ uint32_t pd_h2(float f0, float f1) {
    uint32_t r;
    asm("cvt.rn.f16x2.f32 %0, %1, %2;" : "=r"(r) : "f"(f1), "f"(f0));
    return r;
}

__device__ __forceinline__ void pd_store(float* __restrict__ out, const float* a5,
                                         int pA, int pB, int N, int j, int tg) {
    if (pA < N) {
        float* o = out + 36 * (size_t)pA + 12 * j;
        *(float2*)(o + 2 * tg) = make_float2(a5[0], a5[1]);
        if (tg < 2) *(float2*)(o + 8 + 2 * tg) = make_float2(a5[4], a5[5]);
    }
    if (pB < N) {
        float* o = out + 36 * (size_t)pB + 12 * j;
        *(float2*)(o + 2 * tg) = make_float2(a5[2], a5[3]);
        if (tg < 2) *(float2*)(o + 8 + 2 * tg) = make_float2(a5[6], a5[7]);
    }
}

__global__ void __launch_bounds__(PD_THREADS, 1)
PartialDerivatives_38706245271665_kernel(
    const float* __restrict__ x,
    const float* __restrict__ W1, const float* __restrict__ b1,
    const float* __restrict__ W2, const float* __restrict__ b2,
    const float* __restrict__ W3, const float* __restrict__ b3,
    const float* __restrict__ W4, const float* __restrict__ b4,
    const float* __restrict__ W5,
    float* __restrict__ out, int N)
{
    extern __shared__ uint32_t sm[];
    float* sW1   = (float*)(sm + SM_W1);
    float* sBias = (float*)(sm + SM_BIAS);
    const int tid = threadIdx.x;

    // ---- stage W1 / biases ----
    for (int i = tid; i < 192; i += PD_THREADS) sW1[i] = W1[i];
    for (int i = tid; i < 64; i += PD_THREADS) {
        sBias[i] = b1[i]; sBias[64 + i] = b2[i];
        sBias[128 + i] = b3[i]; sBias[192 + i] = b4[i];
    }
    // ---- stage B' SoA (fp16, single plane): word r = ((kt*4+j)*32+lane)*4+c ----
    for (int i = tid; i < 3 * 2048; i += PD_THREADS) {
        int L = i >> 11, r = i & 2047;
        int c = r & 3, t = r >> 2;
        int lane_ = t & 31, jj = (t >> 5) & 3, kt = t >> 7;
        int tg_ = lane_ & 3, g_ = lane_ >> 2;
        int nt = 2 * jj + (c >> 1), rr = c & 1;
        int k0 = 16 * kt + 2 * tg_ + 8 * rr;
        int n  = 8 * nt + g_;
        const float* W = (L == 0) ? W2 : (L == 1) ? W3 : W4;
        __half2 hh = __floats2half2_rn(W[k0 * 64 + n], W[(k0 + 1) * 64 + n]);
        sm[SM_B + L * 2048 + r] = *(uint32_t*)&hh;
    }
    // ---- stage B5' SoA: word i = (kt*32 + lane)*4 + c ----
    for (int i = tid; i < 512; i += PD_THREADS) {
        int c = i & 3, t = i >> 2;
        int lane_ = t & 31, kt = t >> 5;
        int tg_ = lane_ & 3, g_ = lane_ >> 2;
        int nt = c >> 1, rr = c & 1;
        int k0 = 16 * kt + 2 * tg_ + 8 * rr;
        int n  = 8 * nt + g_;
        float v0 = (n < 12) ? W5[k0 * 12 + n] : 0.0f;
        float v1 = (n < 12) ? W5[(k0 + 1) * 12 + n] : 0.0f;
        __half2 hh = __floats2half2_rn(v0, v1);
        sm[SM_B5 + i] = *(uint32_t*)&hh;
    }
    __syncthreads();

    const int wid  = tid >> 5;
    const int lane = tid & 31;
    const int g    = lane >> 2;
    const int tg   = lane & 3;

    const uint4* Bfrag4  = ((const uint4*)(sm + SM_B))  + lane;   // + L*512 (uint4)
    const uint4* B5frag4 = ((const uint4*)(sm + SM_B5)) + lane;
    // Per-lane A-frag slots for t0/t1/t2 (same-thread rw only, conflict-free).
    uint4* av1 = ((uint4*)sm) + SM_A4 + wid * 384 + lane;
    uint4* av2 = av1 + 128;
    uint4* av3 = av1 + 256;
    // Per-lane dv slots: sdv[nt*32] holds dv[4nt..4nt+3].
    float4* sdv = ((float4*)sm) + SM_DV4 + wid * 256 + lane;

    const int nTiles = (N + 15) >> 4;

    for (int wt = blockIdx.x * PD_NW + wid; wt < nTiles; wt += gridDim.x * PD_NW) {
        const int p0 = wt << 4;
        const int pA = p0 + g, pB = p0 + g + 8;

        uint32_t Ah0[16];   // h fragments in registers

        // ================ layer 1 (K=3), direct into fragments ================
        {
            float xA0 = 0.f, xA1 = 0.f, xA2 = 0.f, xB0 = 0.f, xB1 = 0.f, xB2 = 0.f;
            if (pA < N) {
                const float* xp = x + 3 * (size_t)pA;
                xA0 = __ldg(xp); xA1 = __ldg(xp + 1); xA2 = __ldg(xp + 2);
            }
            if (pB < N) {
                const float* xp = x + 3 * (size_t)pB;
                xB0 = __ldg(xp); xB1 = __ldg(xp + 1); xB2 = __ldg(xp + 2);
            }
            #pragma unroll
            for (int kt = 0; kt < 4; ++kt) {
                uint32_t f1[4], f2[4], f3[4];
                #pragma unroll
                for (int s = 0; s < 2; ++s) {
                    int f0 = 16 * kt + 2 * tg + 8 * s;
                    float2 w0 = *(float2*)&sW1[f0];
                    float2 w1 = *(float2*)&sW1[64 + f0];
                    float2 w2 = *(float2*)&sW1[128 + f0];
                    float2 bb = *(float2*)&sBias[f0];
                    float hA0, dA0, hA1, dA1, hB0, dB0, hB1, dB1;
                    pd_silu_d(fmaf(xA0, w0.x, fmaf(xA1, w1.x, fmaf(xA2, w2.x, bb.x))), hA0, dA0);
                    pd_silu_d(fmaf(xA0, w0.y, fmaf(xA1, w1.y, fmaf(xA2, w2.y, bb.y))), hA1, dA1);
                    pd_silu_d(fmaf(xB0, w0.x, fmaf(xB1, w1.x, fmaf(xB2, w2.x, bb.x))), hB0, dB0);
                    pd_silu_d(fmaf(xB0, w0.y, fmaf(xB1, w1.y, fmaf(xB2, w2.y, bb.y))), hB1, dB1);
                    int fr = kt * 4 + 2 * s;
                    Ah0[fr]     = pd_h2(hA0, hA1);
                    Ah0[fr + 1] = pd_h2(hB0, hB1);
                    f1[2*s]   = pd_h2(w0.x * dA0, w0.y * dA1);
                    f1[2*s+1] = pd_h2(w0.x * dB0, w0.y * dB1);
                    f2[2*s]   = pd_h2(w1.x * dA0, w1.y * dA1);
                    f2[2*s+1] = pd_h2(w1.x * dB0, w1.y * dB1);
                    f3[2*s]   = pd_h2(w2.x * dA0, w2.y * dA1);
                    f3[2*s+1] = pd_h2(w2.x * dB0, w2.y * dB1);
                }
                av1[kt * 32] = make_uint4(f1[0], f1[1], f1[2], f1[3]);
                av2[kt * 32] = make_uint4(f2[0], f2[1], f2[2], f2[3]);
                av3[kt * 32] = make_uint4(f3[0], f3[1], f3[2], f3[3]);
            }
        }

        // ================ layers 2..4: paired MMA + per-kt fused epilogues ================
        #pragma unroll 1
        for (int L = 0; L < 3; ++L) {
            const uint4* Bb4  = Bfrag4 + L * 512;
            const float* bias = sBias + 64 + L * 64;
            const bool lastL  = (L == 2);

            // ---- pair 1: (h regs, t0 smem), shared B loads ----
            {
                float acc0[32], acc1[32];
                #pragma unroll
                for (int q = 0; q < 32; ++q) { acc0[q] = 0.f; acc1[q] = 0.f; }
                pd_gemm64_pair_rs(acc0, acc1, Bb4, Ah0, av1);
                // epilogue fused per kt: silu on acc0 -> h,dv; dv to SMEM;
                // scale acc1 by dv; pack both.
                #pragma unroll
                for (int kt = 0; kt < 4; ++kt) {
                    float hv[8];
                    #pragma unroll
                    for (int s = 0; s < 2; ++s) {
                        int nt = 2 * kt + s;
                        float2 bb = *(float2*)&bias[8 * nt + 2 * tg];
                        float d0, d1, d2, d3;
                        pd_silu_d(acc0[4 * nt + 0] + bb.x, hv[4*s+0], d0);
                        pd_silu_d(acc0[4 * nt + 1] + bb.y, hv[4*s+1], d1);
                        pd_silu_d(acc0[4 * nt + 2] + bb.x, hv[4*s+2], d2);
                        pd_silu_d(acc0[4 * nt + 3] + bb.y, hv[4*s+3], d3);
                        sdv[nt * 32] = make_float4(d0, d1, d2, d3);
                        acc1[4 * nt + 0] *= d0; acc1[4 * nt + 1] *= d1;
                        acc1[4 * nt + 2] *= d2; acc1[4 * nt + 3] *= d3;
                    }
                    if (!lastL) {
                        Ah0[4*kt+0] = pd_h2(hv[0], hv[1]);
                        Ah0[4*kt+1] = pd_h2(hv[2], hv[3]);
                        Ah0[4*kt+2] = pd_h2(hv[4], hv[5]);
                        Ah0[4*kt+3] = pd_h2(hv[6], hv[7]);
                    }
                    av1[kt * 32] = make_uint4(pd_h2(acc1[8*kt+0], acc1[8*kt+1]),
                                              pd_h2(acc1[8*kt+2], acc1[8*kt+3]),
                                              pd_h2(acc1[8*kt+4], acc1[8*kt+5]),
                                              pd_h2(acc1[8*kt+6], acc1[8*kt+7]));
                }
            }
            // ---- pair 2: (t1, t2) smem A, shared B loads ----
            {
                float acc0[32], acc1[32];
                #pragma unroll
                for (int q = 0; q < 32; ++q) { acc0[q] = 0.f; acc1[q] = 0.f; }
                pd_gemm64_pair_ss(acc0, acc1, Bb4, av2, av3);
                #pragma unroll
                for (int kt = 0; kt < 4; ++kt) {
                    float4 dA = sdv[(2 * kt) * 32];
                    float4 dB = sdv[(2 * kt + 1) * 32];
                    acc0[8*kt+0] *= dA.x; acc0[8*kt+1] *= dA.y;
                    acc0[8*kt+2] *= dA.z; acc0[8*kt+3] *= dA.w;
                    acc0[8*kt+4] *= dB.x; acc0[8*kt+5] *= dB.y;
                    acc0[8*kt+6] *= dB.z; acc0[8*kt+7] *= dB.w;
                    acc1[8*kt+0] *= dA.x; acc1[8*kt+1] *= dA.y;
                    acc1[8*kt+2] *= dA.z; acc1[8*kt+3] *= dA.w;
                    acc1[8*kt+4] *= dB.x; acc1[8*kt+5] *= dB.y;
                    acc1[8*kt+6] *= dB.z; acc1[8*kt+7] *= dB.w;
                    av2[kt * 32] = make_uint4(pd_h2(acc0[8*kt+0], acc0[8*kt+1]),
                                              pd_h2(acc0[8*kt+2], acc0[8*kt+3]),
                                              pd_h2(acc0[8*kt+4], acc0[8*kt+5]),
                                              pd_h2(acc0[8*kt+6], acc0[8*kt+7]));
                    av3[kt * 32] = make_uint4(pd_h2(acc1[8*kt+0], acc1[8*kt+1]),
                                              pd_h2(acc1[8*kt+2], acc1[8*kt+3]),
                                              pd_h2(acc1[8*kt+4], acc1[8*kt+5]),
                                              pd_h2(acc1[8*kt+6], acc1[8*kt+7]));
                }
            }
        }

        // ================ layer 5: tri-GEMM, shared B loads ================
        {
            float a50[8], a51[8], a52[8];
            #pragma unroll
            for (int q = 0; q < 8; ++q) { a50[q] = 0.f; a51[q] = 0.f; a52[q] = 0.f; }
            pd_gemm16_tri(a50, a51, a52, B5frag4, av1, av2, av3);
            pd_store(out, a50, pA, pB, N, 0, tg);
            pd_store(out, a51, pA, pB, N, 1, tg);
            pd_store(out, a52, pA, pB, N, 2, tg);
        }
    }
}

extern "C" void kernel_launch(void* const* d_in, const int* in_sizes, int n_in,
                              void* d_out, int out_size)
{
    const float* x  = (const float*)d_in[0];
    const float* W1 = (const float*)d_in[1];
    const float* b1 = (const float*)d_in[2];
    const float* W2 = (const float*)d_in[3];
    const float* b2 = (const float*)d_in[4];
    const float* W3 = (const float*)d_in[5];
    const float* b3 = (const float*)d_in[6];
    const float* W4 = (const float*)d_in[7];
    const float* b4 = (const float*)d_in[8];
    const float* W5 = (const float*)d_in[9];
    // b5 unused: constant offset has zero Jacobian.

    int N = in_sizes[0] / 3;
    int smemBytes = SM_WORDS * (int)sizeof(uint32_t);   // 192256

    cudaFuncSetAttribute(PartialDerivatives_38706245271665_kernel,
                         cudaFuncAttributeMaxDynamicSharedMemorySize, smemBytes);

    // 152 persistent CTAs, 512 threads (16 warps) each -> 1 CTA/SM, 4 warps/SMSP.
    PartialDerivatives_38706245271665_kernel<<<152, PD_THREADS, smemBytes>>>(
        x, W1, b1, W2, b2, W3, b3, W4, b4, W5, (float*)d_out, N);
}

// round 15
// speedup vs baseline: 2.5031x; 1.0245x over previous
#include <cuda_runtime.h>
#include <cuda_fp16.h>
#include <cstdint>

// Jacobian (3x12) of 3->64->64->64->64->12 SiLU MLP at N=1M points.
// mma.sync m16n8k16 fp16, fp32 accum, pure fp16 weights (validated R14).
// One warp owns a 16-point tile + ALL 4 vectors {h,t0,t1,t2}.
// R15: n-half QUAD GEMM — each layer done as two passes over 32 output cols
// with all 4 vectors in flight (acc 4x16 regs):
//   * every B fragment loaded ONCE feeds 4 vectors (B LDS halved again)
//   * dv computed and consumed in-register (dv SMEM roundtrip eliminated)
//   * A-frag SMEM region double-buffered (half-1 epilogue writes next-layer
//     frags while half-2 still reads current ones); h-frags double in regs.
// 512 thr/CTA (4 warps/SMSP); t0,t1,t2 A-frags in per-lane SMEM slots
// (same-thread rw, no sync, SoA conflict-free). tanh.approx sigmoid.
//
// SMEM words: [0,192) W1 | [192,448) b1..b4 | [448,6592) B' L2..4
// (2048 words/layer, SoA slot (kt*4+j)*32+lane) | [6592,7104) B5' |
// [7104,56256) A-frag slots x2 buffers:
//   each buf: 16 warps x 3 vec x 4 kt x 32 lanes x uint4 (24576 words)
#define PD_THREADS 512
#define PD_NW 16
#define SM_W1   0
#define SM_BIAS 192
#define SM_B    448
#define SM_B5   6592
#define SM_A4   1776            /* uint4 index of A-frag area (word 7104/4) */
#define AV_BUF  6144            /* uint4 per A-frag buffer */
#define SM_WORDS (7104 + 2 * 24576)   /* 56256 words = 225024 B */

__device__ __forceinline__ void pd_mma(float* d,
                                       uint32_t a0, uint32_t a1, uint32_t a2, uint32_t a3,
                                       uint32_t b0, uint32_t b1) {
    asm volatile(
        "mma.sync.aligned.m16n8k16.row.col.f32.f16.f16.f32 "
        "{%0,%1,%2,%3},{%4,%5,%6,%7},{%8,%9},{%0,%1,%2,%3};\n"
        : "+f"(d[0]), "+f"(d[1]), "+f"(d[2]), "+f"(d[3])
        : "r"(a0), "r"(a1), "r"(a2), "r"(a3), "r"(b0), "r"(b1));
}

// 4 n-tiles (one n-half) for one vector from two B uint4s.
__device__ __forceinline__ void pd_mma_half(float* acc,
                                            uint32_t a0, uint32_t a1, uint32_t a2, uint32_t a3,
                                            uint4 B0, uint4 B1) {
    pd_mma(acc + 0,  a0, a1, a2, a3, B0.x, B0.y);
    pd_mma(acc + 4,  a0, a1, a2, a3, B0.z, B0.w);
    pd_mma(acc + 8,  a0, a1, a2, a3, B1.x, B1.y);
    pd_mma(acc + 12, a0, a1, a2, a3, B1.z, B1.w);
}

// Layer-5 tri-GEMM (n=16): B loaded once per kt, feeds all 3 tangents (SMEM A).
__device__ __forceinline__ void pd_gemm16_tri(float* a0, float* a1, float* a2,
                                              const uint4* B5b4, const uint4* av1,
                                              const uint4* av2, const uint4* av3) {
    #pragma unroll
    for (int kt = 0; kt < 4; ++kt) {
        uint4 R = av1[kt * 32];
        uint4 P = av2[kt * 32];
        uint4 Q = av3[kt * 32];
        uint4 H = B5b4[kt * 32];
        pd_mma(a0 + 0, R.x, R.y, R.z, R.w, H.x, H.y);
        pd_mma(a0 + 4, R.x, R.y, R.z, R.w, H.z, H.w);
        pd_mma(a1 + 0, P.x, P.y, P.z, P.w, H.x, H.y);
        pd_mma(a1 + 4, P.x, P.y, P.z, P.w, H.z, H.w);
        pd_mma(a2 + 0, Q.x, Q.y, Q.z, Q.w, H.x, H.y);
        pd_mma(a2 + 4, Q.x, Q.y, Q.z, Q.w, H.z, H.w);
    }
}

// silu + silu' via single-MUFU sigmoid: sig = 0.5*tanh(x/2) + 0.5
__device__ __forceinline__ void pd_silu_d(float pre, float& h, float& d) {
    float t;
    asm("tanh.approx.f32 %0, %1;" : "=f"(t) : "f"(0.5f * pre));
    float sig = fmaf(0.5f, t, 0.5f);
    h = pre * sig;
    d = fmaf(h, 1.0f - sig, sig);
}

// pack (f0 -> low half, f1 -> high half) as fp16x2
__device__ __forceinline__ uint32_t pd_h2(float f0, float f1) {
    uint32_t r;
    asm("cvt.rn.f16x2.f32 %0, %1, %2;" : "=r"(r) : "f"(f1), "f"(f0));
    return r;
}

__device__ __forceinline__ void pd_store(float* __restrict__ out, const float* a5,
                                         int pA, int pB, int N, int j, int tg) {
    if (pA < N) {
        float* o = out + 36 * (size_t)pA + 12 * j;
        *(float2*)(o + 2 * tg) = make_float2(a5[0], a5[1]);
        if (tg < 2) *(float2*)(o + 8 + 2 * tg) = make_float2(a5[4], a5[5]);
    }
    if (pB < N) {
        float* o = out + 36 * (size_t)pB + 12 * j;
        *(float2*)(o + 2 * tg) = make_float2(a5[2], a5[3]);
        if (tg < 2) *(float2*)(o + 8 + 2 * tg) = make_float2(a5[6], a5[7]);
    }
}

__global__ void __launch_bounds__(PD_THREADS, 1)
PartialDerivatives_38706245271665_kernel(
    const float* __restrict__ x,
    const float* __restrict__ W1, const float* __restrict__ b1,
    const float* __restrict__ W2, const float* __restrict__ b2,
    const float* __restrict__ W3, const float* __restrict__ b3,
    const float* __restrict__ W4, const float* __restrict__ b4,
    const float* __restrict__ W5,
    float* __restrict__ out, int N)
{
    extern __shared__ uint32_t sm[];
    float* sW1   = (float*)(sm + SM_W1);
    float* sBias = (float*)(sm + SM_BIAS);
    const int tid = threadIdx.x;

    // ---- stage W1 / biases ----
    for (int i = tid; i < 192; i += PD_THREADS) sW1[i] = W1[i];
    for (int i = tid; i < 64; i += PD_THREADS) {
        sBias[i] = b1[i]; sBias[64 + i] = b2[i];
        sBias[128 + i] = b3[i]; sBias[192 + i] = b4[i];
    }
    // ---- stage B' SoA (fp16): word r = ((kt*4+j)*32+lane)*4+c ----
    for (int i = tid; i < 3 * 2048; i += PD_THREADS) {
        int L = i >> 11, r = i & 2047;
        int c = r & 3, t = r >> 2;
        int lane_ = t & 31, jj = (t >> 5) & 3, kt = t >> 7;
        int tg_ = lane_ & 3, g_ = lane_ >> 2;
        int nt = 2 * jj + (c >> 1), rr = c & 1;
        int k0 = 16 * kt + 2 * tg_ + 8 * rr;
        int n  = 8 * nt + g_;
        const float* W = (L == 0) ? W2 : (L == 1) ? W3 : W4;
        __half2 hh = __floats2half2_rn(W[k0 * 64 + n], W[(k0 + 1) * 64 + n]);
        sm[SM_B + L * 2048 + r] = *(uint32_t*)&hh;
    }
    // ---- stage B5' SoA: word i = (kt*32 + lane)*4 + c ----
    for (int i = tid; i < 512; i += PD_THREADS) {
        int c = i & 3, t = i >> 2;
        int lane_ = t & 31, kt = t >> 5;
        int tg_ = lane_ & 3, g_ = lane_ >> 2;
        int nt = c >> 1, rr = c & 1;
        int k0 = 16 * kt + 2 * tg_ + 8 * rr;
        int n  = 8 * nt + g_;
        float v0 = (n < 12) ? W5[k0 * 12 + n] : 0.0f;
        float v1 = (n < 12) ? W5[(k0 + 1) * 12 + n] : 0.0f;
        __half2 hh = __floats2half2_rn(v0, v1);
        sm[SM_B5 + i] = *(uint32_t*)&hh;
    }
    __syncthreads();

    const int wid  = tid >> 5;
    const int lane = tid & 31;
    const int g    = lane >> 2;
    const int tg   = lane & 3;

    const uint4* Bfrag4  = ((const uint4*)(sm + SM_B))  + lane;   // + L*512 (uint4)
    const uint4* B5frag4 = ((const uint4*)(sm + SM_B5)) + lane;
    // Per-lane A-frag slots (t0/t1/t2 at +0/+128/+256), double-buffered.
    uint4* avA = ((uint4*)sm) + SM_A4 + wid * 384 + lane;

    const int nTiles = (N + 15) >> 4;

    for (int wt = blockIdx.x * PD_NW + wid; wt < nTiles; wt += gridDim.x * PD_NW) {
        const int p0 = wt << 4;
        const int pA = p0 + g, pB = p0 + g + 8;

        uint32_t Ah0[16];   // current-layer h fragments (registers)

        // ================ layer 1 (K=3), direct into fragments (buf0) ================
        {
            float xA0 = 0.f, xA1 = 0.f, xA2 = 0.f, xB0 = 0.f, xB1 = 0.f, xB2 = 0.f;
            if (pA < N) {
                const float* xp = x + 3 * (size_t)pA;
                xA0 = __ldg(xp); xA1 = __ldg(xp + 1); xA2 = __ldg(xp + 2);
            }
            if (pB < N) {
                const float* xp = x + 3 * (size_t)pB;
                xB0 = __ldg(xp); xB1 = __ldg(xp + 1); xB2 = __ldg(xp + 2);
            }
            #pragma unroll
            for (int kt = 0; kt < 4; ++kt) {
                uint32_t f1[4], f2[4], f3[4];
                #pragma unroll
                for (int s = 0; s < 2; ++s) {
                    int f0 = 16 * kt + 2 * tg + 8 * s;
                    float2 w0 = *(float2*)&sW1[f0];
                    float2 w1 = *(float2*)&sW1[64 + f0];
                    float2 w2 = *(float2*)&sW1[128 + f0];
                    float2 bb = *(float2*)&sBias[f0];
                    float hA0, dA0, hA1, dA1, hB0, dB0, hB1, dB1;
                    pd_silu_d(fmaf(xA0, w0.x, fmaf(xA1, w1.x, fmaf(xA2, w2.x, bb.x))), hA0, dA0);
                    pd_silu_d(fmaf(xA0, w0.y, fmaf(xA1, w1.y, fmaf(xA2, w2.y, bb.y))), hA1, dA1);
                    pd_silu_d(fmaf(xB0, w0.x, fmaf(xB1, w1.x, fmaf(xB2, w2.x, bb.x))), hB0, dB0);
                    pd_silu_d(fmaf(xB0, w0.y, fmaf(xB1, w1.y, fmaf(xB2, w2.y, bb.y))), hB1, dB1);
                    int fr = kt * 4 + 2 * s;
                    Ah0[fr]     = pd_h2(hA0, hA1);
                    Ah0[fr + 1] = pd_h2(hB0, hB1);
                    f1[2*s]   = pd_h2(w0.x * dA0, w0.y * dA1);
                    f1[2*s+1] = pd_h2(w0.x * dB0, w0.y * dB1);
                    f2[2*s]   = pd_h2(w1.x * dA0, w1.y * dA1);
                    f2[2*s+1] = pd_h2(w1.x * dB0, w1.y * dB1);
                    f3[2*s]   = pd_h2(w2.x * dA0, w2.y * dA1);
                    f3[2*s+1] = pd_h2(w2.x * dB0, w2.y * dB1);
                }
                avA[kt * 32]       = make_uint4(f1[0], f1[1], f1[2], f1[3]);
                avA[128 + kt * 32] = make_uint4(f2[0], f2[1], f2[2], f2[3]);
                avA[256 + kt * 32] = make_uint4(f3[0], f3[1], f3[2], f3[3]);
            }
        }

        // ================ layers 2..4: n-half QUAD GEMM ================
        #pragma unroll 1
        for (int L = 0; L < 3; ++L) {
            const uint4* Bb4  = Bfrag4 + L * 512;
            const float* bias = sBias + 64 + L * 64;
            const bool lastL  = (L == 2);
            const uint4* Ra = avA + ((L & 1) ? AV_BUF : 0);   // read buffer
            uint4*       Wa = avA + ((L & 1) ? 0 : AV_BUF);   // write buffer

            uint32_t Ah0n[16];   // next-layer h fragments

            #pragma unroll
            for (int hf = 0; hf < 2; ++hf) {
                float a0[16], a1[16], a2[16], a3[16];
                #pragma unroll
                for (int q = 0; q < 16; ++q) { a0[q]=0.f; a1[q]=0.f; a2[q]=0.f; a3[q]=0.f; }

                #pragma unroll
                for (int kt = 0; kt < 4; ++kt) {
                    uint32_t p0 = Ah0[4*kt+0], p1 = Ah0[4*kt+1];
                    uint32_t p2 = Ah0[4*kt+2], p3 = Ah0[4*kt+3];
                    uint4 T0 = Ra[kt * 32];
                    uint4 T1 = Ra[128 + kt * 32];
                    uint4 T2 = Ra[256 + kt * 32];
                    uint4 B0 = Bb4[kt * 128 + (2 * hf) * 32];
                    uint4 B1 = Bb4[kt * 128 + (2 * hf + 1) * 32];
                    pd_mma_half(a0, p0, p1, p2, p3, B0, B1);
                    pd_mma_half(a1, T0.x, T0.y, T0.z, T0.w, B0, B1);
                    pd_mma_half(a2, T1.x, T1.y, T1.z, T1.w, B0, B1);
                    pd_mma_half(a3, T2.x, T2.y, T2.z, T2.w, B0, B1);
                }

                // epilogue: per next-layer k-block (s=0,1), dv in registers only
                #pragma unroll
                for (int s = 0; s < 2; ++s) {
                    int ktp = 2 * hf + s;
                    int b = 8 * s;
                    float hv[8], dv[8];
                    #pragma unroll
                    for (int u = 0; u < 2; ++u) {
                        int nt = 4 * hf + 2 * s + u;
                        float2 bb = *(float2*)&bias[8 * nt + 2 * tg];
                        pd_silu_d(a0[b + 4*u + 0] + bb.x, hv[4*u+0], dv[4*u+0]);
                        pd_silu_d(a0[b + 4*u + 1] + bb.y, hv[4*u+1], dv[4*u+1]);
                        pd_silu_d(a0[b + 4*u + 2] + bb.x, hv[4*u+2], dv[4*u+2]);
                        pd_silu_d(a0[b + 4*u + 3] + bb.y, hv[4*u+3], dv[4*u+3]);
                    }
                    if (!lastL) {
                        Ah0n[4*ktp+0] = pd_h2(hv[0], hv[1]);
                        Ah0n[4*ktp+1] = pd_h2(hv[2], hv[3]);
                        Ah0n[4*ktp+2] = pd_h2(hv[4], hv[5]);
                        Ah0n[4*ktp+3] = pd_h2(hv[6], hv[7]);
                    }
                    Wa[ktp * 32] = make_uint4(
                        pd_h2(a1[b+0]*dv[0], a1[b+1]*dv[1]),
                        pd_h2(a1[b+2]*dv[2], a1[b+3]*dv[3]),
                        pd_h2(a1[b+4]*dv[4], a1[b+5]*dv[5]),
                        pd_h2(a1[b+6]*dv[6], a1[b+7]*dv[7]));
                    Wa[128 + ktp * 32] = make_uint4(
                        pd_h2(a2[b+0]*dv[0], a2[b+1]*dv[1]),
                        pd_h2(a2[b+2]*dv[2], a2[b+3]*dv[3]),
                        pd_h2(a2[b+4]*dv[4], a2[b+5]*dv[5]),
                        pd_h2(a2[b+6]*dv[6], a2[b+7]*dv[7]));
                    Wa[256 + ktp * 32] = make_uint4(
                        pd_h2(a3[b+0]*dv[0], a3[b+1]*dv[1]),
                        pd_h2(a3[b+2]*dv[2], a3[b+3]*dv[3]),
                        pd_h2(a3[b+4]*dv[4], a3[b+5]*dv[5]),
                        pd_h2(a3[b+6]*dv[6], a3[b+7]*dv[7]));
                }
            }

            if (!lastL) {
                #pragma unroll
                for (int q = 0; q < 16; ++q) Ah0[q] = Ah0n[q];
            }
        }

        // ================ layer 5: tri-GEMM (reads buf1, written by L=2) ================
        {
            float a50[8], a51[8], a52[8];
            #pragma unroll
            for (int q = 0; q < 8; ++q) { a50[q] = 0.f; a51[q] = 0.f; a52[q] = 0.f; }
            pd_gemm16_tri(a50, a51, a52, B5frag4,
                          avA + AV_BUF, avA + AV_BUF + 128, avA + AV_BUF + 256);
            pd_store(out, a50, pA, pB, N, 0, tg);
            pd_store(out, a51, pA, pB, N, 1, tg);
            pd_store(out, a52, pA, pB, N, 2, tg);
        }
    }
}

extern "C" void kernel_launch(void* const* d_in, const int* in_sizes, int n_in,
                              void* d_out, int out_size)
{
    const float* x  = (const float*)d_in[0];
    const float* W1 = (const float*)d_in[1];
    const float* b1 = (const float*)d_in[2];
    const float* W2 = (const float*)d_in[3];
    const float* b2 = (const float*)d_in[4];
    const float* W3 = (const float*)d_in[5];
    const float* b3 = (const float*)d_in[6];
    const float* W4 = (const float*)d_in[7];
    const float* b4 = (const float*)d_in[8];
    const float* W5 = (const float*)d_in[9];
    // b5 unused: constant offset has zero Jacobian.

    int N = in_sizes[0] / 3;
    int smemBytes = SM_WORDS * (int)sizeof(uint32_t);   // 225024

    cudaFuncSetAttribute(PartialDerivatives_38706245271665_kernel,
                         cudaFuncAttributeMaxDynamicSharedMemorySize, smemBytes);

    // 152 persistent CTAs, 512 threads (16 warps) each -> 1 CTA/SM, 4 warps/SMSP.
    PartialDerivatives_38706245271665_kernel<<<152, PD_THREADS, smemBytes>>>(
        x, W1, b1, W2, b2, W3, b3, W4, b4, W5, (float*)d_out, N);
}

// round 16
// speedup vs baseline: 2.5278x; 1.0099x over previous
#include <cuda_runtime.h>
#include <cuda_fp16.h>
#include <cstdint>

// Jacobian (3x12) of 3->64->64->64->64->12 SiLU MLP at N=1M points.
// mma.sync m16n8k16 fp16, fp32 accum, pure fp16 weights (validated R14).
// One warp owns a 16-point tile + ALL 4 vectors {h,t0,t1,t2}.
// n-half QUAD GEMM (R15): two passes over 32 output cols, all 4 vectors in
// flight; each B fragment loaded once feeds 4 vectors; dv in registers only;
// A-frag SMEM double-buffered. tanh.approx sigmoid.
// R16: (a) next tile's x prefetched right after layer-1 consumes current x
// (LDG latency hidden under the whole tile); (b) Ah0n temp shrunk 16->8 regs
// (hf=1 epilogue writes Ah0 in place) -> ~120 regs, scheduler slack.
//
// SMEM words: [0,192) W1 | [192,448) b1..b4 | [448,6592) B' L2..4
// (2048 words/layer, SoA slot (kt*4+j)*32+lane) | [6592,7104) B5' |
// [7104,56256) A-frag slots x2 buffers (each: 16 warps x 3 vec x 4 kt x 32 x uint4)
#define PD_THREADS 512
#define PD_NW 16
#define SM_W1   0
#define SM_BIAS 192
#define SM_B    448
#define SM_B5   6592
#define SM_A4   1776            /* uint4 index of A-frag area (word 7104/4) */
#define AV_BUF  6144            /* uint4 per A-frag buffer */
#define SM_WORDS (7104 + 2 * 24576)   /* 56256 words = 225024 B */

__device__ __forceinline__ void pd_mma(float* d,
                                       uint32_t a0, uint32_t a1, uint32_t a2, uint32_t a3,
                                       uint32_t b0, uint32_t b1) {
    asm volatile(
        "mma.sync.aligned.m16n8k16.row.col.f32.f16.f16.f32 "
        "{%0,%1,%2,%3},{%4,%5,%6,%7},{%8,%9},{%0,%1,%2,%3};\n"
        : "+f"(d[0]), "+f"(d[1]), "+f"(d[2]), "+f"(d[3])
        : "r"(a0), "r"(a1), "r"(a2), "r"(a3), "r"(b0), "r"(b1));
}

// 4 n-tiles (one n-half) for one vector from two B uint4s.
__device__ __forceinline__ void pd_mma_half(float* acc,
                                            uint32_t a0, uint32_t a1, uint32_t a2, uint32_t a3,
                                            uint4 B0, uint4 B1) {
    pd_mma(acc + 0,  a0, a1, a2, a3, B0.x, B0.y);
    pd_mma(acc + 4,  a0, a1, a2, a3, B0.z, B0.w);
    pd_mma(acc + 8,  a0, a1, a2, a3, B1.x, B1.y);
    pd_mma(acc + 12, a0, a1, a2, a3, B1.z, B1.w);
}

// Layer-5 tri-GEMM (n=16): B loaded once per kt, feeds all 3 tangents (SMEM A).
__device__ __forceinline__ void pd_gemm16_tri(float* a0, float* a1, float* a2,
                                              const uint4* B5b4, const uint4* av1,
                                              const uint4* av2, const uint4* av3) {
    #pragma unroll
    for (int kt = 0; kt < 4; ++kt) {
        uint4 R = av1[kt * 32];
        uint4 P = av2[kt * 32];
        uint4 Q = av3[kt * 32];
        uint4 H = B5b4[kt * 32];
        pd_mma(a0 + 0, R.x, R.y, R.z, R.w, H.x, H.y);
        pd_mma(a0 + 4, R.x, R.y, R.z, R.w, H.z, H.w);
        pd_mma(a1 + 0, P.x, P.y, P.z, P.w, H.x, H.y);
        pd_mma(a1 + 4, P.x, P.y, P.z, P.w, H.z, H.w);
        pd_mma(a2 + 0, Q.x, Q.y, Q.z, Q.w, H.x, H.y);
        pd_mma(a2 + 4, Q.x, Q.y, Q.z, Q.w, H.z, H.w);
    }
}

// silu + silu' via single-MUFU sigmoid: sig = 0.5*tanh(x/2) + 0.5
__device__ __forceinline__ void pd_silu_d(float pre, float& h, float& d) {
    float t;
    asm("tanh.approx.f32 %0, %1;" : "=f"(t) : "f"(0.5f * pre));
    float sig = fmaf(0.5f, t, 0.5f);
    h = pre * sig;
    d = fmaf(h, 1.0f - sig, sig);
}

// pack (f0 -> low half, f1 -> high half) as fp16x2
__device__ __forceinline__ uint32_t pd_h2(float f0, float f1) {
    uint32_t r;
    asm("cvt.rn.f16x2.f32 %0, %1, %2;" : "=r"(r) : "f"(f1), "f"(f0));
    return r;
}

__device__ __forceinline__ void pd_store(float* __restrict__ out, const float* a5,
                                         int pA, int pB, int N, int j, int tg) {
    if (pA < N) {
        float* o = out + 36 * (size_t)pA + 12 * j;
        *(float2*)(o + 2 * tg) = make_float2(a5[0], a5[1]);
        if (tg < 2) *(float2*)(o + 8 + 2 * tg) = make_float2(a5[4], a5[5]);
    }
    if (pB < N) {
        float* o = out + 36 * (size_t)pB + 12 * j;
        *(float2*)(o + 2 * tg) = make_float2(a5[2], a5[3]);
        if (tg < 2) *(float2*)(o + 8 + 2 * tg) = make_float2(a5[6], a5[7]);
    }
}

__global__ void __launch_bounds__(PD_THREADS, 1)
PartialDerivatives_38706245271665_kernel(
    const float* __restrict__ x,
    const float* __restrict__ W1, const float* __restrict__ b1,
    const float* __restrict__ W2, const float* __restrict__ b2,
    const float* __restrict__ W3, const float* __restrict__ b3,
    const float* __restrict__ W4, const float* __restrict__ b4,
    const float* __restrict__ W5,
    float* __restrict__ out, int N)
{
    extern __shared__ uint32_t sm[];
    float* sW1   = (float*)(sm + SM_W1);
    float* sBias = (float*)(sm + SM_BIAS);
    const int tid = threadIdx.x;

    // ---- stage W1 / biases ----
    for (int i = tid; i < 192; i += PD_THREADS) sW1[i] = W1[i];
    for (int i = tid; i < 64; i += PD_THREADS) {
        sBias[i] = b1[i]; sBias[64 + i] = b2[i];
        sBias[128 + i] = b3[i]; sBias[192 + i] = b4[i];
    }
    // ---- stage B' SoA (fp16): word r = ((kt*4+j)*32+lane)*4+c ----
    for (int i = tid; i < 3 * 2048; i += PD_THREADS) {
        int L = i >> 11, r = i & 2047;
        int c = r & 3, t = r >> 2;
        int lane_ = t & 31, jj = (t >> 5) & 3, kt = t >> 7;
        int tg_ = lane_ & 3, g_ = lane_ >> 2;
        int nt = 2 * jj + (c >> 1), rr = c & 1;
        int k0 = 16 * kt + 2 * tg_ + 8 * rr;
        int n  = 8 * nt + g_;
        const float* W = (L == 0) ? W2 : (L == 1) ? W3 : W4;
        __half2 hh = __floats2half2_rn(W[k0 * 64 + n], W[(k0 + 1) * 64 + n]);
        sm[SM_B + L * 2048 + r] = *(uint32_t*)&hh;
    }
    // ---- stage B5' SoA: word i = (kt*32 + lane)*4 + c ----
    for (int i = tid; i < 512; i += PD_THREADS) {
        int c = i & 3, t = i >> 2;
        int lane_ = t & 31, kt = t >> 5;
        int tg_ = lane_ & 3, g_ = lane_ >> 2;
        int nt = c >> 1, rr = c & 1;
        int k0 = 16 * kt + 2 * tg_ + 8 * rr;
        int n  = 8 * nt + g_;
        float v0 = (n < 12) ? W5[k0 * 12 + n] : 0.0f;
        float v1 = (n < 12) ? W5[(k0 + 1) * 12 + n] : 0.0f;
        __half2 hh = __floats2half2_rn(v0, v1);
        sm[SM_B5 + i] = *(uint32_t*)&hh;
    }
    __syncthreads();

    const int wid  = tid >> 5;
    const int lane = tid & 31;
    const int g    = lane >> 2;
    const int tg   = lane & 3;

    const uint4* Bfrag4  = ((const uint4*)(sm + SM_B))  + lane;   // + L*512 (uint4)
    const uint4* B5frag4 = ((const uint4*)(sm + SM_B5)) + lane;
    // Per-lane A-frag slots (t0/t1/t2 at +0/+128/+256), double-buffered.
    uint4* avA = ((uint4*)sm) + SM_A4 + wid * 384 + lane;

    const int nTiles  = (N + 15) >> 4;
    const int wstride = gridDim.x * PD_NW;
    const int wt0     = blockIdx.x * PD_NW + wid;

    // ---- prefetch x for the first tile ----
    float nx0 = 0.f, nx1 = 0.f, nx2 = 0.f, nx3 = 0.f, nx4 = 0.f, nx5 = 0.f;
    if (wt0 < nTiles) {
        int p0 = wt0 << 4;
        int pA = p0 + g, pB = p0 + g + 8;
        if (pA < N) {
            const float* xp = x + 3 * (size_t)pA;
            nx0 = __ldg(xp); nx1 = __ldg(xp + 1); nx2 = __ldg(xp + 2);
        }
        if (pB < N) {
            const float* xp = x + 3 * (size_t)pB;
            nx3 = __ldg(xp); nx4 = __ldg(xp + 1); nx5 = __ldg(xp + 2);
        }
    }

    for (int wt = wt0; wt < nTiles; wt += wstride) {
        const int p0 = wt << 4;
        const int pA = p0 + g, pB = p0 + g + 8;

        const float xA0 = nx0, xA1 = nx1, xA2 = nx2;
        const float xB0 = nx3, xB1 = nx4, xB2 = nx5;

        // ---- prefetch x for the NEXT tile (latency hidden by this tile) ----
        {
            int wtn = wt + wstride;
            nx0 = 0.f; nx1 = 0.f; nx2 = 0.f; nx3 = 0.f; nx4 = 0.f; nx5 = 0.f;
            if (wtn < nTiles) {
                int p0n = wtn << 4;
                int pAn = p0n + g, pBn = p0n + g + 8;
                if (pAn < N) {
                    const float* xp = x + 3 * (size_t)pAn;
                    nx0 = __ldg(xp); nx1 = __ldg(xp + 1); nx2 = __ldg(xp + 2);
                }
                if (pBn < N) {
                    const float* xp = x + 3 * (size_t)pBn;
                    nx3 = __ldg(xp); nx4 = __ldg(xp + 1); nx5 = __ldg(xp + 2);
                }
            }
        }

        uint32_t Ah0[16];   // current-layer h fragments (registers)

        // ================ layer 1 (K=3), direct into fragments (buf0) ================
        {
            #pragma unroll
            for (int kt = 0; kt < 4; ++kt) {
                uint32_t f1[4], f2[4], f3[4];
                #pragma unroll
                for (int s = 0; s < 2; ++s) {
                    int f0 = 16 * kt + 2 * tg + 8 * s;
                    float2 w0 = *(float2*)&sW1[f0];
                    float2 w1 = *(float2*)&sW1[64 + f0];
                    float2 w2 = *(float2*)&sW1[128 + f0];
                    float2 bb = *(float2*)&sBias[f0];
                    float hA0, dA0, hA1, dA1, hB0, dB0, hB1, dB1;
                    pd_silu_d(fmaf(xA0, w0.x, fmaf(xA1, w1.x, fmaf(xA2, w2.x, bb.x))), hA0, dA0);
                    pd_silu_d(fmaf(xA0, w0.y, fmaf(xA1, w1.y, fmaf(xA2, w2.y, bb.y))), hA1, dA1);
                    pd_silu_d(fmaf(xB0, w0.x, fmaf(xB1, w1.x, fmaf(xB2, w2.x, bb.x))), hB0, dB0);
                    pd_silu_d(fmaf(xB0, w0.y, fmaf(xB1, w1.y, fmaf(xB2, w2.y, bb.y))), hB1, dB1);
                    int fr = kt * 4 + 2 * s;
                    Ah0[fr]     = pd_h2(hA0, hA1);
                    Ah0[fr + 1] = pd_h2(hB0, hB1);
                    f1[2*s]   = pd_h2(w0.x * dA0, w0.y * dA1);
                    f1[2*s+1] = pd_h2(w0.x * dB0, w0.y * dB1);
                    f2[2*s]   = pd_h2(w1.x * dA0, w1.y * dA1);
                    f2[2*s+1] = pd_h2(w1.x * dB0, w1.y * dB1);
                    f3[2*s]   = pd_h2(w2.x * dA0, w2.y * dA1);
                    f3[2*s+1] = pd_h2(w2.x * dB0, w2.y * dB1);
                }
                avA[kt * 32]       = make_uint4(f1[0], f1[1], f1[2], f1[3]);
                avA[128 + kt * 32] = make_uint4(f2[0], f2[1], f2[2], f2[3]);
                avA[256 + kt * 32] = make_uint4(f3[0], f3[1], f3[2], f3[3]);
            }
        }

        // ================ layers 2..4: n-half QUAD GEMM ================
        #pragma unroll 1
        for (int L = 0; L < 3; ++L) {
            const uint4* Bb4  = Bfrag4 + L * 512;
            const float* bias = sBias + 64 + L * 64;
            const bool lastL  = (L == 2);
            const uint4* Ra = avA + ((L & 1) ? AV_BUF : 0);   // read buffer
            uint4*       Wa = avA + ((L & 1) ? 0 : AV_BUF);   // write buffer

            uint32_t Ah0n[8];   // next-layer h fragments, k-blocks 0..1 only
                                // (hf=1 epilogue writes Ah0[8..15] in place:
                                //  the hf=1 GEMM was their last reader)

            #pragma unroll
            for (int hf = 0; hf < 2; ++hf) {
                float a0[16], a1[16], a2[16], a3[16];
                #pragma unroll
                for (int q = 0; q < 16; ++q) { a0[q]=0.f; a1[q]=0.f; a2[q]=0.f; a3[q]=0.f; }

                #pragma unroll
                for (int kt = 0; kt < 4; ++kt) {
                    uint32_t p0 = Ah0[4*kt+0], p1 = Ah0[4*kt+1];
                    uint32_t p2 = Ah0[4*kt+2], p3 = Ah0[4*kt+3];
                    uint4 T0 = Ra[kt * 32];
                    uint4 T1 = Ra[128 + kt * 32];
                    uint4 T2 = Ra[256 + kt * 32];
                    uint4 B0 = Bb4[kt * 128 + (2 * hf) * 32];
                    uint4 B1 = Bb4[kt * 128 + (2 * hf + 1) * 32];
                    pd_mma_half(a0, p0, p1, p2, p3, B0, B1);
                    pd_mma_half(a1, T0.x, T0.y, T0.z, T0.w, B0, B1);
                    pd_mma_half(a2, T1.x, T1.y, T1.z, T1.w, B0, B1);
                    pd_mma_half(a3, T2.x, T2.y, T2.z, T2.w, B0, B1);
                }

                // epilogue: per next-layer k-block (s=0,1), dv in registers only
                #pragma unroll
                for (int s = 0; s < 2; ++s) {
                    int ktp = 2 * hf + s;
                    int b = 8 * s;
                    float hv[8], dv[8];
                    #pragma unroll
                    for (int u = 0; u < 2; ++u) {
                        int nt = 4 * hf + 2 * s + u;
                        float2 bb = *(float2*)&bias[8 * nt + 2 * tg];
                        pd_silu_d(a0[b + 4*u + 0] + bb.x, hv[4*u+0], dv[4*u+0]);
                        pd_silu_d(a0[b + 4*u + 1] + bb.y, hv[4*u+1], dv[4*u+1]);
                        pd_silu_d(a0[b + 4*u + 2] + bb.x, hv[4*u+2], dv[4*u+2]);
                        pd_silu_d(a0[b + 4*u + 3] + bb.y, hv[4*u+3], dv[4*u+3]);
                    }
                    if (!lastL) {
                        if (hf == 0) {
                            Ah0n[4*ktp+0] = pd_h2(hv[0], hv[1]);
                            Ah0n[4*ktp+1] = pd_h2(hv[2], hv[3]);
                            Ah0n[4*ktp+2] = pd_h2(hv[4], hv[5]);
                            Ah0n[4*ktp+3] = pd_h2(hv[6], hv[7]);
                        } else {
                            Ah0[4*ktp+0] = pd_h2(hv[0], hv[1]);
                            Ah0[4*ktp+1] = pd_h2(hv[2], hv[3]);
                            Ah0[4*ktp+2] = pd_h2(hv[4], hv[5]);
                            Ah0[4*ktp+3] = pd_h2(hv[6], hv[7]);
                        }
                    }
                    Wa[ktp * 32] = make_uint4(
                        pd_h2(a1[b+0]*dv[0], a1[b+1]*dv[1]),
                        pd_h2(a1[b+2]*dv[2], a1[b+3]*dv[3]),
                        pd_h2(a1[b+4]*dv[4], a1[b+5]*dv[5]),
                        pd_h2(a1[b+6]*dv[6], a1[b+7]*dv[7]));
                    Wa[128 + ktp * 32] = make_uint4(
                        pd_h2(a2[b+0]*dv[0], a2[b+1]*dv[1]),
                        pd_h2(a2[b+2]*dv[2], a2[b+3]*dv[3]),
                        pd_h2(a2[b+4]*dv[4], a2[b+5]*dv[5]),
                        pd_h2(a2[b+6]*dv[6], a2[b+7]*dv[7]));
                    Wa[256 + ktp * 32] = make_uint4(
                        pd_h2(a3[b+0]*dv[0], a3[b+1]*dv[1]),
                        pd_h2(a3[b+2]*dv[2], a3[b+3]*dv[3]),
                        pd_h2(a3[b+4]*dv[4], a3[b+5]*dv[5]),
                        pd_h2(a3[b+6]*dv[6], a3[b+7]*dv[7]));
                }
            }

            if (!lastL) {
                #pragma unroll
                for (int q = 0; q < 8; ++q) Ah0[q] = Ah0n[q];
            }
        }

        // ================ layer 5: tri-GEMM (reads buf1, written by L=2) ================
        {
            float a50[8], a51[8], a52[8];
            #pragma unroll
            for (int q = 0; q < 8; ++q) { a50[q] = 0.f; a51[q] = 0.f; a52[q] = 0.f; }
            pd_gemm16_tri(a50, a51, a52, B5frag4,
                          avA + AV_BUF, avA + AV_BUF + 128, avA + AV_BUF + 256);
            pd_store(out, a50, pA, pB, N, 0, tg);
            pd_store(out, a51, pA, pB, N, 1, tg);
            pd_store(out, a52, pA, pB, N, 2, tg);
        }
    }
}

extern "C" void kernel_launch(void* const* d_in, const int* in_sizes, int n_in,
                              void* d_out, int out_size)
{
    const float* x  = (const float*)d_in[0];
    const float* W1 = (const float*)d_in[1];
    const float* b1 = (const float*)d_in[2];
    const float* W2 = (const float*)d_in[3];
    const float* b2 = (const float*)d_in[4];
    const float* W3 = (const float*)d_in[5];
    const float* b3 = (const float*)d_in[6];
    const float* W4 = (const float*)d_in[7];
    const float* b4 = (const float*)d_in[8];
    const float* W5 = (const float*)d_in[9];
    // b5 unused: constant offset has zero Jacobian.

    int N = in_sizes[0] / 3;
    int smemBytes = SM_WORDS * (int)sizeof(uint32_t);   // 225024

    cudaFuncSetAttribute(PartialDerivatives_38706245271665_kernel,
                         cudaFuncAttributeMaxDynamicSharedMemorySize, smemBytes);

    // 152 persistent CTAs, 512 threads (16 warps) each -> 1 CTA/SM, 4 warps/SMSP.
    PartialDerivatives_38706245271665_kernel<<<152, PD_THREADS, smemBytes>>>(
        x, W1, b1, W2, b2, W3, b3, W4, b4, W5, (float*)d_out, N);
}